// round 1
// baseline (speedup 1.0000x reference)
#include <cuda_runtime.h>
#include <cuda_bf16.h>
#include <math.h>

// Problem-instance maxima (N=10000, M=50000, fixed shapes per reference)
#define NMAX 10016
#define D_IN 32
#define DOUT 64
#define EMB 256
#define EPS 1e-5f
// log2(e)/TEMP,  TEMP = 0.2
#define SIM_SCALE 7.2134752044448170f

// ---------------- scratch (static device globals; no allocation) -------------
__device__ float g_prod[3 * NMAX * D_IN];   // normalized riemannian features
__device__ float g_x2n[NMAX * EMB];         // row-normalized x2
__device__ float g_xn[NMAX * EMB];          // row-normalized x
__device__ float g_H[4 * NMAX * 192];       // per-product MLP-layer-1 partials
__device__ float g_rowsum[NMAX];
__device__ float g_colsum[NMAX];
__device__ float g_diag[NMAX];
__device__ double g_macc;                   // sum of all log-sigmoid terms

// ---------------- zero accumulators ------------------------------------------
__global__ void zero_kernel(int N) {
    int i = blockIdx.x * blockDim.x + threadIdx.x;
    if (i < N) { g_rowsum[i] = 0.f; g_colsum[i] = 0.f; }
    if (i == 0) g_macc = 0.0;
}

// ---------------- normalize feats -> products --------------------------------
// one warp per row; d == 32 == warp width
__global__ void norm_feats_kernel(const float* __restrict__ feats,
                                  const float* __restrict__ ks, int N) {
    int row = (blockIdx.x * blockDim.x + threadIdx.x) >> 5;   // 0 .. 3N-1
    int lane = threadIdx.x & 31;
    if (row >= 3 * N) return;
    float v = feats[row * D_IN + lane];
    float sq = v * v;
    #pragma unroll
    for (int off = 16; off; off >>= 1) sq += __shfl_xor_sync(0xffffffffu, sq, off);
    int f = row / N;
    float k = ks[f];
    float scale = 0.45f / (sqrtf(sq) * sqrtf(fabsf(k)));   // 0.9*0.5 * radius / ||x||
    g_prod[row * D_IN + lane] = v * scale;
}

// ---------------- build x2 (random mapping) and row-normalize ----------------
// one block (256 threads) per row n; thread t handles output column t
__global__ void build_x2_kernel(const float* __restrict__ feat_free,
                                const float* __restrict__ ks,
                                const float* __restrict__ Ws,
                                const float* __restrict__ bias,
                                const float* __restrict__ W_free,
                                const float* __restrict__ b_free,
                                int N) {
    __shared__ float xi[4][D_IN];
    __shared__ float red[256];
    int n = blockIdx.x;
    int t = threadIdx.x;
    if (t < 96) {
        int f = t / 32, c = t % 32;
        xi[f][c] = g_prod[(f * N + n) * D_IN + c];
    } else if (t < 128) {
        xi[3][t - 96] = feat_free[n * D_IN + (t - 96)];
    }
    __syncthreads();

    int f = t >> 6;        // factor 0..3
    int col = t & 63;      // output col within factor
    float z;
    if (f < 3) {
        float k = ks[f];
        float nsq = 0.f;
        #pragma unroll
        for (int c = 0; c < D_IN; c++) nsq += xi[f][c] * xi[f][c];
        float div = 0.f;
        const float* w = Ws + (f * DOUT + col) * D_IN;
        #pragma unroll
        for (int c = 0; c < D_IN; c++) {
            float dd = xi[f][c] - w[c];
            div += dd * dd;
        }
        float num = 1.f + k * nsq;
        float dist = logf(num / (div + EPS));
        z = expf(15.5f * dist) * cosf(dist + bias[f * DOUT + col]);   // (d-1)*0.5 = 15.5
    } else {
        float dot = 0.f;
        const float* w = W_free + col * D_IN;
        #pragma unroll
        for (int c = 0; c < D_IN; c++) dot += xi[3][c] * w[c];
        z = expf(15.5f * dot) * cosf(dot + b_free[col]);
    }

    red[t] = z * z;
    __syncthreads();
    #pragma unroll
    for (int s = 128; s > 0; s >>= 1) {
        if (t < s) red[t] += red[t + s];
        __syncthreads();
    }
    float inv = rsqrtf(red[0]);
    g_x2n[n * EMB + t] = z * inv;
}

// ---------------- normalize x rows -------------------------------------------
__global__ void norm_x_kernel(const float* __restrict__ x, int N) {
    __shared__ float red[256];
    int n = blockIdx.x;
    int t = threadIdx.x;
    float v = x[n * EMB + t];
    red[t] = v * v;
    __syncthreads();
    #pragma unroll
    for (int s = 128; s > 0; s >>= 1) {
        if (t < s) red[t] += red[t + s];
        __syncthreads();
    }
    float inv = rsqrtf(red[0]);
    g_xn[n * EMB + t] = v * inv;
}

// ---------------- fused sim GEMM + exp + row/col/diag reduction ---------------
// C[i,j] = xn[i,:] . x2n[j,:]; e = exp(C/T); accumulate rowsum_i, colsum_j, diag
#define TILE 128
__global__ __launch_bounds__(256) void sim_gemm_kernel(int N) {
    __shared__ float As[8][TILE];
    __shared__ float Bs[8][TILE];
    __shared__ float sRow[TILE];
    __shared__ float sCol[TILE];

    int i0 = blockIdx.y * TILE;
    int j0 = blockIdx.x * TILE;
    int t = threadIdx.x;
    int tx = t & 15;    // col group
    int ty = t >> 4;    // row group

    float acc[8][8];
    #pragma unroll
    for (int r = 0; r < 8; r++)
        #pragma unroll
        for (int c = 0; c < 8; c++) acc[r][c] = 0.f;

    int lr = t >> 1;            // row within tile for the load
    int lk = (t & 1) * 4;       // k offset (0 or 4)
    const float* A = g_xn;
    const float* B = g_x2n;

    for (int k0 = 0; k0 < EMB; k0 += 8) {
        float4 av = make_float4(0.f, 0.f, 0.f, 0.f);
        float4 bv = make_float4(0.f, 0.f, 0.f, 0.f);
        int ar = i0 + lr;
        int br = j0 + lr;
        if (ar < N) av = *(const float4*)(A + ar * EMB + k0 + lk);
        if (br < N) bv = *(const float4*)(B + br * EMB + k0 + lk);
        __syncthreads();
        As[lk + 0][lr] = av.x; As[lk + 1][lr] = av.y;
        As[lk + 2][lr] = av.z; As[lk + 3][lr] = av.w;
        Bs[lk + 0][lr] = bv.x; Bs[lk + 1][lr] = bv.y;
        Bs[lk + 2][lr] = bv.z; Bs[lk + 3][lr] = bv.w;
        __syncthreads();
        #pragma unroll
        for (int kk = 0; kk < 8; kk++) {
            float a[8], b[8];
            *(float4*)(a)     = *(const float4*)&As[kk][ty * 8];
            *(float4*)(a + 4) = *(const float4*)&As[kk][ty * 8 + 4];
            *(float4*)(b)     = *(const float4*)&Bs[kk][tx * 8];
            *(float4*)(b + 4) = *(const float4*)&Bs[kk][tx * 8 + 4];
            #pragma unroll
            for (int r = 0; r < 8; r++)
                #pragma unroll
                for (int c = 0; c < 8; c++)
                    acc[r][c] += a[r] * b[c];
        }
    }

    // epilogue: exp + partial row/col sums + diagonal
    float rp[8], cp[8];
    #pragma unroll
    for (int r = 0; r < 8; r++) { rp[r] = 0.f; cp[r] = 0.f; }
    #pragma unroll
    for (int r = 0; r < 8; r++) {
        int i = i0 + ty * 8 + r;
        #pragma unroll
        for (int c = 0; c < 8; c++) {
            int j = j0 + tx * 8 + c;
            if (i < N && j < N) {
                float e = exp2f(acc[r][c] * SIM_SCALE);
                rp[r] += e;
                cp[c] += e;
                if (i == j) g_diag[i] = e;
            }
        }
    }

    __syncthreads();
    if (t < TILE) { sRow[t] = 0.f; sCol[t] = 0.f; }
    __syncthreads();

    // row partials: reduce across tx (low 4 lane bits) via shuffle
    #pragma unroll
    for (int r = 0; r < 8; r++) {
        float v = rp[r];
        #pragma unroll
        for (int off = 1; off < 16; off <<= 1) v += __shfl_xor_sync(0xffffffffu, v, off);
        if (tx == 0) atomicAdd(&sRow[ty * 8 + r], v);
    }
    // col partials: reduce across the 2 ty values in a warp via shuffle(16)
    #pragma unroll
    for (int c = 0; c < 8; c++) {
        float v = cp[c];
        v += __shfl_xor_sync(0xffffffffu, v, 16);
        if ((t & 16) == 0) atomicAdd(&sCol[tx * 8 + c], v);
    }
    __syncthreads();

    if (t < TILE) {
        int i = i0 + t;
        if (i < N) atomicAdd(&g_rowsum[i], sRow[t]);
        int j = j0 + t;
        if (j < N) atomicAdd(&g_colsum[j], sCol[t]);
    }
}

// ---------------- precompute H = product_p @ W1 (split in 3 parts) -----------
// thread per (p, n, j);  j = part*64 + jj
__global__ void build_H_kernel(const float* __restrict__ feat_free,
                               const float* __restrict__ W1, int N) {
    int id = blockIdx.x * blockDim.x + threadIdx.x;
    int total = 4 * N * 192;
    if (id >= total) return;
    int p = id / (N * 192);
    int rem = id % (N * 192);
    int n = rem / 192;
    int j = rem % 192;
    int part = j >> 6;
    int jj = j & 63;
    const float* row = (p < 3) ? (g_prod + (p * N + n) * D_IN)
                               : (feat_free + n * D_IN);
    float s = 0.f;
    #pragma unroll
    for (int c = 0; c < D_IN; c++)
        s += row[c] * W1[(part * 32 + c) * 64 + jj];
    g_H[(p * N + n) * 192 + j] = s;
}

// ---------------- motif loss: warp per (product, sign, motif) ----------------
__global__ void motif_kernel(const int* __restrict__ motif,
                             const int* __restrict__ neg_uv,
                             const float* __restrict__ b1,
                             const float* __restrict__ W2,
                             const float* __restrict__ b2,
                             int N, int M) {
    __shared__ double sd[8];
    int gwarp = (blockIdx.x * blockDim.x + threadIdx.x) >> 5;
    int lane = threadIdx.x & 31;
    int wib = threadIdx.x >> 5;
    int total = 4 * 2 * M;
    double local = 0.0;

    if (gwarp < total) {
        int p = gwarp / (2 * M);
        int rem = gwarp % (2 * M);
        int s = rem / M;
        int m = rem % M;
        int u, v, w;
        if (s == 0) { u = motif[m];  v = motif[M + m];  w = motif[2 * M + m]; }
        else        { u = neg_uv[m]; v = neg_uv[M + m]; w = motif[2 * M + m]; }
        const float* base = g_H + (size_t)p * N * 192;
        float acc = 0.f;
        #pragma unroll
        for (int rep = 0; rep < 2; rep++) {
            int j = lane + rep * 32;
            float h = base[(size_t)u * 192 + j]
                    + base[(size_t)v * 192 + 64 + j]
                    + base[(size_t)w * 192 + 128 + j]
                    + b1[j];
            h = fmaxf(h, 0.f);
            acc += h * W2[j];
        }
        #pragma unroll
        for (int off = 16; off; off >>= 1) acc += __shfl_xor_sync(0xffffffffu, acc, off);
        if (lane == 0) {
            float logit = acc + b2[0];
            float z = s ? -logit : logit;
            // stable log-sigmoid
            float ls = fminf(z, 0.f) - log1pf(expf(-fabsf(z)));
            local = (double)ls;
        }
    }
    if (lane == 0) sd[wib] = local;
    __syncthreads();
    if (threadIdx.x == 0) {
        double sum = 0.0;
        #pragma unroll
        for (int i = 0; i < 8; i++) sum += sd[i];
        atomicAdd(&g_macc, sum);
    }
}

// ---------------- finalize: cl loss + motif loss -> scalar -------------------
__global__ void finalize_kernel(float* __restrict__ out, int N, int M) {
    __shared__ double red[256];
    int t = threadIdx.x;
    double l = 0.0;
    for (int j = t; j < N; j += 256) {
        double pos = (double)g_diag[j];
        double lp = log(pos);
        l += (lp - log((double)g_colsum[j] - pos));   // loss_1 term
        l += (lp - log((double)g_rowsum[j] - pos));   // loss_2 term
    }
    red[t] = l;
    __syncthreads();
    #pragma unroll
    for (int s = 128; s > 0; s >>= 1) {
        if (t < s) red[t] += red[t + s];
        __syncthreads();
    }
    if (t == 0) {
        double cl = -0.5 * red[0] / (double)N;
        double motif_loss = -g_macc / (double)M;
        out[0] = (float)(cl + motif_loss);
    }
}

// ---------------- launch ------------------------------------------------------
extern "C" void kernel_launch(void* const* d_in, const int* in_sizes, int n_in,
                              void* d_out, int out_size) {
    const float* x         = (const float*)d_in[0];
    const float* feats     = (const float*)d_in[1];
    const float* feat_free = (const float*)d_in[2];
    const float* ks        = (const float*)d_in[3];
    const float* Ws        = (const float*)d_in[4];
    const float* bias      = (const float*)d_in[5];
    const float* W_free    = (const float*)d_in[6];
    const float* b_free    = (const float*)d_in[7];
    const float* W1        = (const float*)d_in[8];
    const float* b1        = (const float*)d_in[9];
    const float* W2        = (const float*)d_in[10];
    const float* b2        = (const float*)d_in[11];
    const int*   motif     = (const int*)d_in[12];
    const int*   neg_uv    = (const int*)d_in[13];
    float* out = (float*)d_out;

    int N = in_sizes[0] / EMB;        // 10000
    int M = in_sizes[12] / 3;         // 50000

    // zero accumulators
    zero_kernel<<<(N + 255) / 256, 256>>>(N);

    // normalize riemannian features (3N rows, warp per row)
    {
        int rows = 3 * N;
        int blocks = (rows * 32 + 255) / 256;
        norm_feats_kernel<<<blocks, 256>>>(feats, ks, N);
    }

    // build x2 (row-normalized) and normalized x
    build_x2_kernel<<<N, 256>>>(feat_free, ks, Ws, bias, W_free, b_free, N);
    norm_x_kernel<<<N, 256>>>(x, N);

    // fused sim GEMM + softmax-denominator reductions
    {
        int nt = (N + TILE - 1) / TILE;
        dim3 grid(nt, nt);
        sim_gemm_kernel<<<grid, 256>>>(N);
    }

    // motif loss
    {
        int total = 4 * N * 192;
        build_H_kernel<<<(total + 255) / 256, 256>>>(feat_free, W1, N);
        int warps = 4 * 2 * M;
        int blocks = (warps * 32 + 255) / 256;
        motif_kernel<<<blocks, 256>>>(motif, neg_uv, b1, W2, b2, N, M);
    }

    finalize_kernel<<<1, 256>>>(out, N, M);
}

// round 2
// speedup vs baseline: 1.5612x; 1.5612x over previous
#include <cuda_runtime.h>
#include <cuda_bf16.h>
#include <math.h>

// Problem-instance maxima (N=10000, M=50000, fixed shapes per reference)
#define NMAX 10016
#define D_IN 32
#define DOUT 64
#define EMB 256
#define EPS 1e-5f
// log2(e)/TEMP,  TEMP = 0.2
#define SIM_SCALE 7.2134752044448170f

// ---------------- scratch (static device globals; no allocation) -------------
__device__ float g_prod[3 * NMAX * D_IN];   // normalized riemannian features
__device__ float g_x2n[NMAX * EMB];         // row-normalized x2 (tf32-rounded)
__device__ float g_xn[NMAX * EMB];          // row-normalized x  (tf32-rounded)
__device__ float g_H[4 * NMAX * 192];       // per-product MLP-layer-1 partials
__device__ float g_rowsum[NMAX];
__device__ float g_colsum[NMAX];
__device__ float g_diag[NMAX];
__device__ double g_macc;                   // sum of all log-sigmoid terms

__device__ __forceinline__ float to_tf32(float x) {
    unsigned u;
    asm("cvt.rna.tf32.f32 %0, %1;" : "=r"(u) : "f"(x));
    return __uint_as_float(u);
}

// ---------------- zero accumulators ------------------------------------------
__global__ void zero_kernel(int N) {
    int i = blockIdx.x * blockDim.x + threadIdx.x;
    if (i < N) { g_rowsum[i] = 0.f; g_colsum[i] = 0.f; }
    if (i == 0) g_macc = 0.0;
}

// ---------------- normalize feats -> products --------------------------------
__global__ void norm_feats_kernel(const float* __restrict__ feats,
                                  const float* __restrict__ ks, int N) {
    int row = (blockIdx.x * blockDim.x + threadIdx.x) >> 5;   // 0 .. 3N-1
    int lane = threadIdx.x & 31;
    if (row >= 3 * N) return;
    float v = feats[row * D_IN + lane];
    float sq = v * v;
    #pragma unroll
    for (int off = 16; off; off >>= 1) sq += __shfl_xor_sync(0xffffffffu, sq, off);
    int f = row / N;
    float k = ks[f];
    float scale = 0.45f / (sqrtf(sq) * sqrtf(fabsf(k)));
    g_prod[row * D_IN + lane] = v * scale;
}

// ---------------- build x2 (random mapping) and row-normalize ----------------
__global__ void build_x2_kernel(const float* __restrict__ feat_free,
                                const float* __restrict__ ks,
                                const float* __restrict__ Ws,
                                const float* __restrict__ bias,
                                const float* __restrict__ W_free,
                                const float* __restrict__ b_free,
                                int N) {
    __shared__ float xi[4][D_IN];
    __shared__ float red[256];
    int n = blockIdx.x;
    int t = threadIdx.x;
    if (t < 96) {
        int f = t / 32, c = t % 32;
        xi[f][c] = g_prod[(f * N + n) * D_IN + c];
    } else if (t < 128) {
        xi[3][t - 96] = feat_free[n * D_IN + (t - 96)];
    }
    __syncthreads();

    int f = t >> 6;
    int col = t & 63;
    float z;
    if (f < 3) {
        float k = ks[f];
        float nsq = 0.f;
        #pragma unroll
        for (int c = 0; c < D_IN; c++) nsq += xi[f][c] * xi[f][c];
        float div = 0.f;
        const float* w = Ws + (f * DOUT + col) * D_IN;
        #pragma unroll
        for (int c = 0; c < D_IN; c++) {
            float dd = xi[f][c] - w[c];
            div += dd * dd;
        }
        float num = 1.f + k * nsq;
        float dist = logf(num / (div + EPS));
        z = expf(15.5f * dist) * cosf(dist + bias[f * DOUT + col]);
    } else {
        float dot = 0.f;
        const float* w = W_free + col * D_IN;
        #pragma unroll
        for (int c = 0; c < D_IN; c++) dot += xi[3][c] * w[c];
        z = expf(15.5f * dot) * cosf(dot + b_free[col]);
    }

    red[t] = z * z;
    __syncthreads();
    #pragma unroll
    for (int s = 128; s > 0; s >>= 1) {
        if (t < s) red[t] += red[t + s];
        __syncthreads();
    }
    float inv = rsqrtf(red[0]);
    g_x2n[n * EMB + t] = to_tf32(z * inv);
}

// ---------------- normalize x rows -------------------------------------------
__global__ void norm_x_kernel(const float* __restrict__ x, int N) {
    __shared__ float red[256];
    int n = blockIdx.x;
    int t = threadIdx.x;
    float v = x[n * EMB + t];
    red[t] = v * v;
    __syncthreads();
    #pragma unroll
    for (int s = 128; s > 0; s >>= 1) {
        if (t < s) red[t] += red[t + s];
        __syncthreads();
    }
    float inv = rsqrtf(red[0]);
    g_xn[n * EMB + t] = to_tf32(v * inv);
}

// ---------------- fused sim GEMM (tf32 mma) + exp + reductions ----------------
// C[i,j] = xn[i,:].x2n[j,:]; e = exp2(C*SIM_SCALE); rowsum_i += e; colsum_j += e
#define TILE 128
#define BK 16
#define SST 136   // smem k-major row stride (conflict-free fragment loads)

__global__ __launch_bounds__(256) void sim_gemm_kernel(int N) {
    __shared__ float As[BK][SST];
    __shared__ float Bs[BK][SST];
    __shared__ float sRow[TILE];
    __shared__ float sCol[TILE];

    const int i0 = blockIdx.y * TILE;
    const int j0 = blockIdx.x * TILE;
    const int t = threadIdx.x;
    const int lane = t & 31;
    const int warp = t >> 5;
    const int wm = warp & 3;          // 0..3 -> 32-row strip
    const int wn = warp >> 2;         // 0..1 -> 64-col strip
    const int g = lane >> 2;          // groupID 0..7
    const int tig = lane & 3;         // 0..3

    float acc[2][8][4];
    #pragma unroll
    for (int mt = 0; mt < 2; mt++)
        #pragma unroll
        for (int nt = 0; nt < 8; nt++)
            #pragma unroll
            for (int c = 0; c < 4; c++) acc[mt][nt][c] = 0.f;

    const float* A = g_xn;
    const float* B = g_x2n;

    // global-load assignment: 2 float4 per thread per matrix per ktile
    const int l0 = t * 2;
    const int row0 = l0 >> 2, kq0 = l0 & 3;
    const int row1 = (l0 + 1) >> 2, kq1 = (l0 + 1) & 3;

    float4 rA0, rA1, rB0, rB1;
    const float4 z4 = make_float4(0.f, 0.f, 0.f, 0.f);

    // prefetch ktile 0
    {
        int ka = 0;
        rA0 = (i0 + row0 < N) ? *(const float4*)(A + (size_t)(i0 + row0) * EMB + ka + kq0 * 4) : z4;
        rA1 = (i0 + row1 < N) ? *(const float4*)(A + (size_t)(i0 + row1) * EMB + ka + kq1 * 4) : z4;
        rB0 = (j0 + row0 < N) ? *(const float4*)(B + (size_t)(j0 + row0) * EMB + ka + kq0 * 4) : z4;
        rB1 = (j0 + row1 < N) ? *(const float4*)(B + (size_t)(j0 + row1) * EMB + ka + kq1 * 4) : z4;
    }

    #pragma unroll 1
    for (int kt = 0; kt < EMB / BK; kt++) {
        // store current tile (transposed to k-major)
        As[kq0 * 4 + 0][row0] = rA0.x; As[kq0 * 4 + 1][row0] = rA0.y;
        As[kq0 * 4 + 2][row0] = rA0.z; As[kq0 * 4 + 3][row0] = rA0.w;
        As[kq1 * 4 + 0][row1] = rA1.x; As[kq1 * 4 + 1][row1] = rA1.y;
        As[kq1 * 4 + 2][row1] = rA1.z; As[kq1 * 4 + 3][row1] = rA1.w;
        Bs[kq0 * 4 + 0][row0] = rB0.x; Bs[kq0 * 4 + 1][row0] = rB0.y;
        Bs[kq0 * 4 + 2][row0] = rB0.z; Bs[kq0 * 4 + 3][row0] = rB0.w;
        Bs[kq1 * 4 + 0][row1] = rB1.x; Bs[kq1 * 4 + 1][row1] = rB1.y;
        Bs[kq1 * 4 + 2][row1] = rB1.z; Bs[kq1 * 4 + 3][row1] = rB1.w;
        __syncthreads();

        // prefetch next tile
        if (kt + 1 < EMB / BK) {
            int ka = (kt + 1) * BK;
            rA0 = (i0 + row0 < N) ? *(const float4*)(A + (size_t)(i0 + row0) * EMB + ka + kq0 * 4) : z4;
            rA1 = (i0 + row1 < N) ? *(const float4*)(A + (size_t)(i0 + row1) * EMB + ka + kq1 * 4) : z4;
            rB0 = (j0 + row0 < N) ? *(const float4*)(B + (size_t)(j0 + row0) * EMB + ka + kq0 * 4) : z4;
            rB1 = (j0 + row1 < N) ? *(const float4*)(B + (size_t)(j0 + row1) * EMB + ka + kq1 * 4) : z4;
        }

        // compute: 2 k-steps of m16n8k8 tf32 mma
        #pragma unroll
        for (int ks = 0; ks < 2; ks++) {
            const int k0 = ks * 8;
            unsigned a[2][4], b[8][2];
            #pragma unroll
            for (int mt = 0; mt < 2; mt++) {
                int mb = wm * 32 + mt * 16 + g;
                a[mt][0] = __float_as_uint(As[k0 + tig][mb]);
                a[mt][1] = __float_as_uint(As[k0 + tig][mb + 8]);
                a[mt][2] = __float_as_uint(As[k0 + tig + 4][mb]);
                a[mt][3] = __float_as_uint(As[k0 + tig + 4][mb + 8]);
            }
            #pragma unroll
            for (int nt = 0; nt < 8; nt++) {
                int nb = wn * 64 + nt * 8 + g;
                b[nt][0] = __float_as_uint(Bs[k0 + tig][nb]);
                b[nt][1] = __float_as_uint(Bs[k0 + tig + 4][nb]);
            }
            #pragma unroll
            for (int mt = 0; mt < 2; mt++)
                #pragma unroll
                for (int nt = 0; nt < 8; nt++) {
                    asm volatile(
                        "mma.sync.aligned.m16n8k8.row.col.f32.tf32.tf32.f32 "
                        "{%0,%1,%2,%3}, {%4,%5,%6,%7}, {%8,%9}, {%0,%1,%2,%3};"
                        : "+f"(acc[mt][nt][0]), "+f"(acc[mt][nt][1]),
                          "+f"(acc[mt][nt][2]), "+f"(acc[mt][nt][3])
                        : "r"(a[mt][0]), "r"(a[mt][1]), "r"(a[mt][2]), "r"(a[mt][3]),
                          "r"(b[nt][0]), "r"(b[nt][1]));
                }
        }
        __syncthreads();
    }

    // ---------------- epilogue: exp + row/col/diag ----------------
    if (t < TILE) { sRow[t] = 0.f; sCol[t] = 0.f; }
    __syncthreads();

    float rp[4];   // rows: mt*2 + {lo,hi}
    float cp[16];  // cols: nt*2 + parity
    #pragma unroll
    for (int r = 0; r < 4; r++) rp[r] = 0.f;
    #pragma unroll
    for (int c = 0; c < 16; c++) cp[c] = 0.f;

    #pragma unroll
    for (int mt = 0; mt < 2; mt++) {
        int i_lo = i0 + wm * 32 + mt * 16 + g;
        int i_hi = i_lo + 8;
        #pragma unroll
        for (int nt = 0; nt < 8; nt++) {
            int j_e = j0 + wn * 64 + nt * 8 + 2 * tig;
            int j_o = j_e + 1;
            if (i_lo < N) {
                if (j_e < N) {
                    float e = exp2f(acc[mt][nt][0] * SIM_SCALE);
                    rp[mt * 2] += e; cp[nt * 2] += e;
                    if (i_lo == j_e) g_diag[i_lo] = e;
                }
                if (j_o < N) {
                    float e = exp2f(acc[mt][nt][1] * SIM_SCALE);
                    rp[mt * 2] += e; cp[nt * 2 + 1] += e;
                    if (i_lo == j_o) g_diag[i_lo] = e;
                }
            }
            if (i_hi < N) {
                if (j_e < N) {
                    float e = exp2f(acc[mt][nt][2] * SIM_SCALE);
                    rp[mt * 2 + 1] += e; cp[nt * 2] += e;
                    if (i_hi == j_e) g_diag[i_hi] = e;
                }
                if (j_o < N) {
                    float e = exp2f(acc[mt][nt][3] * SIM_SCALE);
                    rp[mt * 2 + 1] += e; cp[nt * 2 + 1] += e;
                    if (i_hi == j_o) g_diag[i_hi] = e;
                }
            }
        }
    }

    // row partials: reduce across tig (lane bits 0-1)
    #pragma unroll
    for (int r = 0; r < 4; r++) {
        float v = rp[r];
        v += __shfl_xor_sync(0xffffffffu, v, 1);
        v += __shfl_xor_sync(0xffffffffu, v, 2);
        if (tig == 0) {
            int mt = r >> 1, h = r & 1;
            atomicAdd(&sRow[wm * 32 + mt * 16 + h * 8 + g], v);
        }
    }
    // col partials: reduce across g (lane bits 2-4)
    #pragma unroll
    for (int c = 0; c < 16; c++) {
        float v = cp[c];
        v += __shfl_xor_sync(0xffffffffu, v, 4);
        v += __shfl_xor_sync(0xffffffffu, v, 8);
        v += __shfl_xor_sync(0xffffffffu, v, 16);
        if (g == 0) {
            int nt = c >> 1, par = c & 1;
            atomicAdd(&sCol[wn * 64 + nt * 8 + 2 * tig + par], v);
        }
    }
    __syncthreads();

    if (t < TILE) {
        int i = i0 + t;
        if (i < N) atomicAdd(&g_rowsum[i], sRow[t]);
        int j = j0 + t;
        if (j < N) atomicAdd(&g_colsum[j], sCol[t]);
    }
}

// ---------------- precompute H = product_p @ W1 (split in 3 parts) -----------
__global__ void build_H_kernel(const float* __restrict__ feat_free,
                               const float* __restrict__ W1, int N) {
    int id = blockIdx.x * blockDim.x + threadIdx.x;
    int total = 4 * N * 192;
    if (id >= total) return;
    int p = id / (N * 192);
    int rem = id % (N * 192);
    int n = rem / 192;
    int j = rem % 192;
    int part = j >> 6;
    int jj = j & 63;
    const float* row = (p < 3) ? (g_prod + (p * N + n) * D_IN)
                               : (feat_free + n * D_IN);
    float s = 0.f;
    #pragma unroll
    for (int c = 0; c < D_IN; c++)
        s += row[c] * W1[(part * 32 + c) * 64 + jj];
    g_H[(p * N + n) * 192 + j] = s;
}

// ---------------- motif loss: warp per (product, sign, motif) ----------------
__global__ void motif_kernel(const int* __restrict__ motif,
                             const int* __restrict__ neg_uv,
                             const float* __restrict__ b1,
                             const float* __restrict__ W2,
                             const float* __restrict__ b2,
                             int N, int M) {
    __shared__ double sd[8];
    int gwarp = (blockIdx.x * blockDim.x + threadIdx.x) >> 5;
    int lane = threadIdx.x & 31;
    int wib = threadIdx.x >> 5;
    int total = 4 * 2 * M;
    double local = 0.0;

    if (gwarp < total) {
        int p = gwarp / (2 * M);
        int rem = gwarp % (2 * M);
        int s = rem / M;
        int m = rem % M;
        int u, v, w;
        if (s == 0) { u = motif[m];  v = motif[M + m];  w = motif[2 * M + m]; }
        else        { u = neg_uv[m]; v = neg_uv[M + m]; w = motif[2 * M + m]; }
        const float* base = g_H + (size_t)p * N * 192;
        float acc = 0.f;
        #pragma unroll
        for (int rep = 0; rep < 2; rep++) {
            int j = lane + rep * 32;
            float h = base[(size_t)u * 192 + j]
                    + base[(size_t)v * 192 + 64 + j]
                    + base[(size_t)w * 192 + 128 + j]
                    + b1[j];
            h = fmaxf(h, 0.f);
            acc += h * W2[j];
        }
        #pragma unroll
        for (int off = 16; off; off >>= 1) acc += __shfl_xor_sync(0xffffffffu, acc, off);
        if (lane == 0) {
            float logit = acc + b2[0];
            float z = s ? -logit : logit;
            float ls = fminf(z, 0.f) - log1pf(expf(-fabsf(z)));
            local = (double)ls;
        }
    }
    if (lane == 0) sd[wib] = local;
    __syncthreads();
    if (threadIdx.x == 0) {
        double sum = 0.0;
        #pragma unroll
        for (int i = 0; i < 8; i++) sum += sd[i];
        atomicAdd(&g_macc, sum);
    }
}

// ---------------- finalize ----------------------------------------------------
__global__ void finalize_kernel(float* __restrict__ out, int N, int M) {
    __shared__ double red[256];
    int t = threadIdx.x;
    double l = 0.0;
    for (int j = t; j < N; j += 256) {
        double pos = (double)g_diag[j];
        double lp = log(pos);
        l += (lp - log((double)g_colsum[j] - pos));
        l += (lp - log((double)g_rowsum[j] - pos));
    }
    red[t] = l;
    __syncthreads();
    #pragma unroll
    for (int s = 128; s > 0; s >>= 1) {
        if (t < s) red[t] += red[t + s];
        __syncthreads();
    }
    if (t == 0) {
        double cl = -0.5 * red[0] / (double)N;
        double motif_loss = -g_macc / (double)M;
        out[0] = (float)(cl + motif_loss);
    }
}

// ---------------- launch ------------------------------------------------------
extern "C" void kernel_launch(void* const* d_in, const int* in_sizes, int n_in,
                              void* d_out, int out_size) {
    const float* x         = (const float*)d_in[0];
    const float* feats     = (const float*)d_in[1];
    const float* feat_free = (const float*)d_in[2];
    const float* ks        = (const float*)d_in[3];
    const float* Ws        = (const float*)d_in[4];
    const float* bias      = (const float*)d_in[5];
    const float* W_free    = (const float*)d_in[6];
    const float* b_free    = (const float*)d_in[7];
    const float* W1        = (const float*)d_in[8];
    const float* b1        = (const float*)d_in[9];
    const float* W2        = (const float*)d_in[10];
    const float* b2        = (const float*)d_in[11];
    const int*   motif     = (const int*)d_in[12];
    const int*   neg_uv    = (const int*)d_in[13];
    float* out = (float*)d_out;

    int N = in_sizes[0] / EMB;        // 10000
    int M = in_sizes[12] / 3;         // 50000

    zero_kernel<<<(N + 255) / 256, 256>>>(N);

    {
        int rows = 3 * N;
        int blocks = (rows * 32 + 255) / 256;
        norm_feats_kernel<<<blocks, 256>>>(feats, ks, N);
    }

    build_x2_kernel<<<N, 256>>>(feat_free, ks, Ws, bias, W_free, b_free, N);
    norm_x_kernel<<<N, 256>>>(x, N);

    {
        int nt = (N + TILE - 1) / TILE;
        dim3 grid(nt, nt);
        sim_gemm_kernel<<<grid, 256>>>(N);
    }

    {
        int total = 4 * N * 192;
        build_H_kernel<<<(total + 255) / 256, 256>>>(feat_free, W1, N);
        int warps = 4 * 2 * M;
        int blocks = (warps * 32 + 255) / 256;
        motif_kernel<<<blocks, 256>>>(motif, neg_uv, b1, W2, b2, N, M);
    }

    finalize_kernel<<<1, 256>>>(out, N, M);
}

// round 4
// speedup vs baseline: 1.9666x; 1.2596x over previous
#include <cuda_runtime.h>
#include <cuda_bf16.h>
#include <math.h>
#include <stdint.h>

// Problem-instance maxima (N=10000, M=50000, fixed shapes per reference)
#define NMAX 10016
#define D_IN 32
#define DOUT 64
#define EMB 256
#define EPS 1e-5f
// log2(e)/TEMP,  TEMP = 0.2
#define SIM_SCALE 7.2134752044448170f

// ---------------- scratch (static device globals; no allocation) -------------
__device__ float g_prod[3 * NMAX * D_IN];             // normalized riemannian feats
__device__ __nv_bfloat16 g_xa[NMAX * EMB];            // row-normalized x   (bf16)
__device__ __nv_bfloat16 g_xb[NMAX * EMB];            // row-normalized x2  (bf16)
__device__ float g_H[4 * NMAX * 192];                 // MLP layer-1 partials
__device__ float g_rowsum[NMAX];
__device__ float g_colsum[NMAX];
__device__ float g_diag[NMAX];
__device__ double g_macc;

__device__ __forceinline__ uint32_t smem_u32(const void* p) {
    uint32_t a;
    asm("{ .reg .u64 t; cvta.to.shared.u64 t, %1; cvt.u32.u64 %0, t; }" : "=r"(a) : "l"(p));
    return a;
}

// ---------------- zero accumulators ------------------------------------------
__global__ void zero_kernel(int N) {
    int i = blockIdx.x * blockDim.x + threadIdx.x;
    if (i < N) { g_rowsum[i] = 0.f; g_colsum[i] = 0.f; }
    if (i == 0) g_macc = 0.0;
}

// ---------------- normalize feats -> products --------------------------------
__global__ void norm_feats_kernel(const float* __restrict__ feats,
                                  const float* __restrict__ ks, int N) {
    int row = (blockIdx.x * blockDim.x + threadIdx.x) >> 5;
    int lane = threadIdx.x & 31;
    if (row >= 3 * N) return;
    float v = feats[row * D_IN + lane];
    float sq = v * v;
    #pragma unroll
    for (int off = 16; off; off >>= 1) sq += __shfl_xor_sync(0xffffffffu, sq, off);
    int f = row / N;
    float k = ks[f];
    float scale = 0.45f / (sqrtf(sq) * sqrtf(fabsf(k)));
    g_prod[row * D_IN + lane] = v * scale;
}

// ---------------- build x2 (random mapping), normalize, -> bf16 ---------------
__global__ void build_x2_kernel(const float* __restrict__ feat_free,
                                const float* __restrict__ ks,
                                const float* __restrict__ Ws,
                                const float* __restrict__ bias,
                                const float* __restrict__ W_free,
                                const float* __restrict__ b_free,
                                int N) {
    __shared__ float xi[4][D_IN];
    __shared__ float red[256];
    int n = blockIdx.x;
    int t = threadIdx.x;
    if (t < 96) {
        int f = t / 32, c = t % 32;
        xi[f][c] = g_prod[(f * N + n) * D_IN + c];
    } else if (t < 128) {
        xi[3][t - 96] = feat_free[n * D_IN + (t - 96)];
    }
    __syncthreads();

    int f = t >> 6;
    int col = t & 63;
    float z;
    if (f < 3) {
        float k = ks[f];
        float nsq = 0.f;
        #pragma unroll
        for (int c = 0; c < D_IN; c++) nsq += xi[f][c] * xi[f][c];
        float div = 0.f;
        const float* w = Ws + (f * DOUT + col) * D_IN;
        #pragma unroll
        for (int c = 0; c < D_IN; c++) {
            float dd = xi[f][c] - w[c];
            div += dd * dd;
        }
        float num = 1.f + k * nsq;
        float dist = logf(num / (div + EPS));
        z = expf(15.5f * dist) * cosf(dist + bias[f * DOUT + col]);
    } else {
        float dot = 0.f;
        const float* w = W_free + col * D_IN;
        #pragma unroll
        for (int c = 0; c < D_IN; c++) dot += xi[3][c] * w[c];
        z = expf(15.5f * dot) * cosf(dot + b_free[col]);
    }

    red[t] = z * z;
    __syncthreads();
    #pragma unroll
    for (int s = 128; s > 0; s >>= 1) {
        if (t < s) red[t] += red[t + s];
        __syncthreads();
    }
    float inv = rsqrtf(red[0]);
    g_xb[n * EMB + t] = __float2bfloat16(z * inv);
}

// ---------------- normalize x rows -> bf16 ------------------------------------
__global__ void norm_x_kernel(const float* __restrict__ x, int N) {
    __shared__ float red[256];
    int n = blockIdx.x;
    int t = threadIdx.x;
    float v = x[n * EMB + t];
    red[t] = v * v;
    __syncthreads();
    #pragma unroll
    for (int s = 128; s > 0; s >>= 1) {
        if (t < s) red[t] += red[t + s];
        __syncthreads();
    }
    float inv = rsqrtf(red[0]);
    g_xa[n * EMB + t] = __float2bfloat16(v * inv);
}

// ---------------- sim GEMM: bf16 mma.sync + ldmatrix + fused epilogue ---------
// tile 128x128, full K=256 in smem. 8 warps: warp_m in {0,1} (64 rows),
// warp_n in {0..3} (32 cols). warp tile = 4x4 of m16n8k16.
#define TILE 128
#define ASTRIDE 264    // bf16 elements per smem row (stride 528B: conflict-free)

__global__ __launch_bounds__(256, 1) void sim_hmma_kernel(int N) {
    extern __shared__ __nv_bfloat16 sm[];
    __shared__ float sRow[TILE];
    __shared__ float sCol[TILE];

    __nv_bfloat16* As = sm;                       // 128 x 264
    __nv_bfloat16* Bs = sm + TILE * ASTRIDE;      // 128 x 264

    const int t = threadIdx.x;
    const int lane = t & 31;
    const int wid = t >> 5;
    const int warp_m = wid & 1;
    const int warp_n = wid >> 1;
    const int g = lane >> 2;       // 0..7
    const int tig = lane & 3;      // 0..3
    const int i0 = blockIdx.y * TILE;
    const int j0 = blockIdx.x * TILE;

    // ---- load A and B tiles (full K), 16B chunks, zero-fill OOB rows --------
    const uint4 z4 = make_uint4(0u, 0u, 0u, 0u);
    const uint4* GA = (const uint4*)g_xa;    // 32 chunks of 8 bf16 per row
    const uint4* GB = (const uint4*)g_xb;
    #pragma unroll
    for (int it = 0; it < 16; it++) {
        int id = t + it * 256;               // 0..4095
        int row = id >> 5, cc = id & 31;
        uint4 va = (i0 + row < N) ? GA[(size_t)(i0 + row) * 32 + cc] : z4;
        *(uint4*)(As + row * ASTRIDE + cc * 8) = va;
        uint4 vb = (j0 + row < N) ? GB[(size_t)(j0 + row) * 32 + cc] : z4;
        *(uint4*)(Bs + row * ASTRIDE + cc * 8) = vb;
    }
    if (t < TILE) { sRow[t] = 0.f; sCol[t] = 0.f; }
    __syncthreads();

    const uint32_t aBase = smem_u32(As);
    const uint32_t bBase = smem_u32(Bs);

    float acc[4][4][4];
    #pragma unroll
    for (int mt = 0; mt < 4; mt++)
        #pragma unroll
        for (int nt = 0; nt < 4; nt++)
            #pragma unroll
            for (int c = 0; c < 4; c++) acc[mt][nt][c] = 0.f;

    // ldmatrix lane->address offsets
    const int aRow = lane & 15;             // rows 0..15 within 16x16 tile
    const int aCol = (lane >> 4) * 8;       // k sub-col 0 or 8
    const int bRow = (lane & 7) + ((lane >> 4) << 3);   // n rows: 0-7 then 8-15
    const int bCol = ((lane >> 3) & 1) * 8;             // k sub-col 0 or 8

    #pragma unroll
    for (int kstep = 0; kstep < 16; kstep++) {
        const int k0 = kstep * 16;
        uint32_t a[4][4];
        #pragma unroll
        for (int mt = 0; mt < 4; mt++) {
            uint32_t addr = aBase +
                ((warp_m * 64 + mt * 16 + aRow) * ASTRIDE + k0 + aCol) * 2;
            asm volatile("ldmatrix.sync.aligned.m8n8.x4.shared.b16 {%0,%1,%2,%3}, [%4];"
                         : "=r"(a[mt][0]), "=r"(a[mt][1]), "=r"(a[mt][2]), "=r"(a[mt][3])
                         : "r"(addr));
        }
        uint32_t b[4][2];
        #pragma unroll
        for (int bq = 0; bq < 2; bq++) {
            uint32_t addr = bBase +
                ((warp_n * 32 + bq * 16 + bRow) * ASTRIDE + k0 + bCol) * 2;
            uint32_t r0, r1, r2, r3;
            asm volatile("ldmatrix.sync.aligned.m8n8.x4.shared.b16 {%0,%1,%2,%3}, [%4];"
                         : "=r"(r0), "=r"(r1), "=r"(r2), "=r"(r3)
                         : "r"(addr));
            b[bq * 2][0] = r0;     b[bq * 2][1] = r1;
            b[bq * 2 + 1][0] = r2; b[bq * 2 + 1][1] = r3;
        }
        #pragma unroll
        for (int mt = 0; mt < 4; mt++)
            #pragma unroll
            for (int nt = 0; nt < 4; nt++) {
                asm volatile(
                    "mma.sync.aligned.m16n8k16.row.col.f32.bf16.bf16.f32 "
                    "{%0,%1,%2,%3}, {%4,%5,%6,%7}, {%8,%9}, {%0,%1,%2,%3};"
                    : "+f"(acc[mt][nt][0]), "+f"(acc[mt][nt][1]),
                      "+f"(acc[mt][nt][2]), "+f"(acc[mt][nt][3])
                    : "r"(a[mt][0]), "r"(a[mt][1]), "r"(a[mt][2]), "r"(a[mt][3]),
                      "r"(b[nt][0]), "r"(b[nt][1]));
            }
    }

    // ---- epilogue: exp2 + row/col/diag reductions -----------------------------
    float rp[8];    // mt*2 + {lo,hi}
    float cp[8];    // nt*2 + parity
    #pragma unroll
    for (int r = 0; r < 8; r++) { rp[r] = 0.f; cp[r] = 0.f; }

    #pragma unroll
    for (int mt = 0; mt < 4; mt++) {
        int i_lo = i0 + warp_m * 64 + mt * 16 + g;
        int i_hi = i_lo + 8;
        #pragma unroll
        for (int nt = 0; nt < 4; nt++) {
            int j_e = j0 + warp_n * 32 + nt * 8 + 2 * tig;
            int j_o = j_e + 1;
            if (i_lo < N) {
                if (j_e < N) {
                    float e = exp2f(acc[mt][nt][0] * SIM_SCALE);
                    rp[mt * 2] += e; cp[nt * 2] += e;
                    if (i_lo == j_e) g_diag[i_lo] = e;
                }
                if (j_o < N) {
                    float e = exp2f(acc[mt][nt][1] * SIM_SCALE);
                    rp[mt * 2] += e; cp[nt * 2 + 1] += e;
                    if (i_lo == j_o) g_diag[i_lo] = e;
                }
            }
            if (i_hi < N) {
                if (j_e < N) {
                    float e = exp2f(acc[mt][nt][2] * SIM_SCALE);
                    rp[mt * 2 + 1] += e; cp[nt * 2] += e;
                    if (i_hi == j_e) g_diag[i_hi] = e;
                }
                if (j_o < N) {
                    float e = exp2f(acc[mt][nt][3] * SIM_SCALE);
                    rp[mt * 2 + 1] += e; cp[nt * 2 + 1] += e;
                    if (i_hi == j_o) g_diag[i_hi] = e;
                }
            }
        }
    }

    // rows: reduce across tig (lane bits 0-1)
    #pragma unroll
    for (int r = 0; r < 8; r++) {
        float v = rp[r];
        v += __shfl_xor_sync(0xffffffffu, v, 1);
        v += __shfl_xor_sync(0xffffffffu, v, 2);
        if (tig == 0) {
            int mt = r >> 1, h = r & 1;
            atomicAdd(&sRow[warp_m * 64 + mt * 16 + h * 8 + g], v);
        }
    }
    // cols: reduce across g (lane bits 2-4)
    #pragma unroll
    for (int c = 0; c < 8; c++) {
        float v = cp[c];
        v += __shfl_xor_sync(0xffffffffu, v, 4);
        v += __shfl_xor_sync(0xffffffffu, v, 8);
        v += __shfl_xor_sync(0xffffffffu, v, 16);
        if (g == 0) {
            int nt = c >> 1, par = c & 1;
            atomicAdd(&sCol[warp_n * 32 + nt * 8 + 2 * tig + par], v);
        }
    }
    __syncthreads();

    if (t < TILE) {
        int i = i0 + t;
        if (i < N) atomicAdd(&g_rowsum[i], sRow[t]);
        int j = j0 + t;
        if (j < N) atomicAdd(&g_colsum[j], sCol[t]);
    }
}

// ---------------- precompute H = product_p @ W1 (4 outputs/thread) -----------
__global__ void build_H_kernel(const float* __restrict__ feat_free,
                               const float* __restrict__ W1, int N) {
    int id = blockIdx.x * blockDim.x + threadIdx.x;
    int total = 4 * N * 48;
    if (id >= total) return;
    int p = id / (N * 48);
    int rem = id % (N * 48);
    int n = rem / 48;
    int jg = rem % 48;
    int part = jg >> 4;
    int jj = (jg & 15) * 4;
    const float* row = (p < 3) ? (g_prod + (p * N + n) * D_IN)
                               : (feat_free + n * D_IN);
    float4 s = make_float4(0.f, 0.f, 0.f, 0.f);
    #pragma unroll
    for (int cq = 0; cq < 8; cq++) {
        float4 rv = *(const float4*)(row + cq * 4);
        float rr[4] = {rv.x, rv.y, rv.z, rv.w};
        #pragma unroll
        for (int u = 0; u < 4; u++) {
            int c = cq * 4 + u;
            float4 w = *(const float4*)(W1 + (size_t)(part * 32 + c) * 64 + jj);
            s.x += rr[u] * w.x; s.y += rr[u] * w.y;
            s.z += rr[u] * w.z; s.w += rr[u] * w.w;
        }
    }
    *(float4*)(g_H + (size_t)(p * N + n) * 192 + part * 64 + jj) = s;
}

// ---------------- motif loss: warp per (product, sign, motif) ----------------
__global__ void motif_kernel(const int* __restrict__ motif,
                             const int* __restrict__ neg_uv,
                             const float* __restrict__ b1,
                             const float* __restrict__ W2,
                             const float* __restrict__ b2,
                             int N, int M) {
    __shared__ double sd[8];
    int gwarp = (blockIdx.x * blockDim.x + threadIdx.x) >> 5;
    int lane = threadIdx.x & 31;
    int wib = threadIdx.x >> 5;
    int total = 4 * 2 * M;
    double local = 0.0;

    if (gwarp < total) {
        int p = gwarp / (2 * M);
        int rem = gwarp % (2 * M);
        int s = rem / M;
        int m = rem % M;
        int u, v, w;
        if (s == 0) { u = motif[m];  v = motif[M + m];  w = motif[2 * M + m]; }
        else        { u = neg_uv[m]; v = neg_uv[M + m]; w = motif[2 * M + m]; }
        const float* base = g_H + (size_t)p * N * 192;
        float acc = 0.f;
        #pragma unroll
        for (int rep = 0; rep < 2; rep++) {
            int j = lane + rep * 32;
            float h = base[(size_t)u * 192 + j]
                    + base[(size_t)v * 192 + 64 + j]
                    + base[(size_t)w * 192 + 128 + j]
                    + b1[j];
            h = fmaxf(h, 0.f);
            acc += h * W2[j];
        }
        #pragma unroll
        for (int off = 16; off; off >>= 1) acc += __shfl_xor_sync(0xffffffffu, acc, off);
        if (lane == 0) {
            float logit = acc + b2[0];
            float z = s ? -logit : logit;
            float ls = fminf(z, 0.f) - log1pf(expf(-fabsf(z)));
            local = (double)ls;
        }
    }
    if (lane == 0) sd[wib] = local;
    __syncthreads();
    if (threadIdx.x == 0) {
        double sum = 0.0;
        #pragma unroll
        for (int i = 0; i < 8; i++) sum += sd[i];
        atomicAdd(&g_macc, sum);
    }
}

// ---------------- finalize ----------------------------------------------------
__global__ void finalize_kernel(float* __restrict__ out, int N, int M) {
    __shared__ double red[256];
    int t = threadIdx.x;
    double l = 0.0;
    for (int j = t; j < N; j += 256) {
        double pos = (double)g_diag[j];
        double lp = log(pos);
        l += (lp - log((double)g_colsum[j] - pos));
        l += (lp - log((double)g_rowsum[j] - pos));
    }
    red[t] = l;
    __syncthreads();
    #pragma unroll
    for (int s = 128; s > 0; s >>= 1) {
        if (t < s) red[t] += red[t + s];
        __syncthreads();
    }
    if (t == 0) {
        double cl = -0.5 * red[0] / (double)N;
        double motif_loss = -g_macc / (double)M;
        out[0] = (float)(cl + motif_loss);
    }
}

// ---------------- launch ------------------------------------------------------
extern "C" void kernel_launch(void* const* d_in, const int* in_sizes, int n_in,
                              void* d_out, int out_size) {
    const float* x         = (const float*)d_in[0];
    const float* feats     = (const float*)d_in[1];
    const float* feat_free = (const float*)d_in[2];
    const float* ks        = (const float*)d_in[3];
    const float* Ws        = (const float*)d_in[4];
    const float* bias      = (const float*)d_in[5];
    const float* W_free    = (const float*)d_in[6];
    const float* b_free    = (const float*)d_in[7];
    const float* W1        = (const float*)d_in[8];
    const float* b1        = (const float*)d_in[9];
    const float* W2        = (const float*)d_in[10];
    const float* b2        = (const float*)d_in[11];
    const int*   motif     = (const int*)d_in[12];
    const int*   neg_uv    = (const int*)d_in[13];
    float* out = (float*)d_out;

    int N = in_sizes[0] / EMB;        // 10000
    int M = in_sizes[12] / 3;         // 50000

    const int SMEM_BYTES = 2 * TILE * ASTRIDE * sizeof(__nv_bfloat16);  // 135168
    cudaFuncSetAttribute(sim_hmma_kernel,
                         cudaFuncAttributeMaxDynamicSharedMemorySize, SMEM_BYTES);

    zero_kernel<<<(N + 255) / 256, 256>>>(N);

    {
        int rows = 3 * N;
        int blocks = (rows * 32 + 255) / 256;
        norm_feats_kernel<<<blocks, 256>>>(feats, ks, N);
    }

    build_x2_kernel<<<N, 256>>>(feat_free, ks, Ws, bias, W_free, b_free, N);
    norm_x_kernel<<<N, 256>>>(x, N);

    {
        dim3 grid((N + TILE - 1) / TILE, (N + TILE - 1) / TILE);
        sim_hmma_kernel<<<grid, 256, SMEM_BYTES>>>(N);
    }

    {
        int total = 4 * N * 48;
        build_H_kernel<<<(total + 255) / 256, 256>>>(feat_free, W1, N);
        int warps = 4 * 2 * M;
        int blocks = (warps * 32 + 255) / 256;
        motif_kernel<<<blocks, 256>>>(motif, neg_uv, b1, W2, b2, N, M);
    }

    finalize_kernel<<<1, 256>>>(out, N, M);
}

// round 5
// speedup vs baseline: 2.2105x; 1.1240x over previous
#include <cuda_runtime.h>
#include <cuda_bf16.h>
#include <math.h>
#include <stdint.h>

// Problem-instance maxima (N=10000, M=50000, fixed shapes per reference)
#define NMAX 10016
#define D_IN 32
#define DOUT 64
#define EMB 256
#define EPS 1e-5f
// log2(e)/TEMP,  TEMP = 0.2
#define SIM_SCALE 7.2134752044448170f

// ---------------- scratch (static device globals; no allocation) -------------
__device__ float g_prod[3 * NMAX * D_IN];             // normalized riemannian feats
__device__ __nv_bfloat16 g_xa[NMAX * EMB];            // row-normalized x   (bf16)
__device__ __nv_bfloat16 g_xb[NMAX * EMB];            // row-normalized x2  (bf16)
__device__ float g_H[4 * NMAX * 192];                 // MLP layer-1 partials
__device__ float g_rowsum[NMAX];
__device__ float g_colsum[NMAX];
__device__ float g_diag[NMAX];
__device__ double g_macc;

__device__ __forceinline__ uint32_t smem_u32(const void* p) {
    uint32_t a;
    asm("{ .reg .u64 t; cvta.to.shared.u64 t, %1; cvt.u32.u64 %0, t; }" : "=r"(a) : "l"(p));
    return a;
}
__device__ __forceinline__ void cp_async16(uint32_t dst, const void* src, bool pred) {
    int sz = pred ? 16 : 0;
    asm volatile("cp.async.cg.shared.global [%0], [%1], 16, %2;"
                 :: "r"(dst), "l"(src), "r"(sz) : "memory");
}
#define CP_COMMIT() asm volatile("cp.async.commit_group;" ::: "memory")
#define CP_WAIT(n)  asm volatile("cp.async.wait_group %0;" :: "n"(n) : "memory")

// ---------------- normalize feats -> products --------------------------------
__global__ void norm_feats_kernel(const float* __restrict__ feats,
                                  const float* __restrict__ ks, int N) {
    int row = (blockIdx.x * blockDim.x + threadIdx.x) >> 5;
    int lane = threadIdx.x & 31;
    if (row >= 3 * N) return;
    float v = feats[row * D_IN + lane];
    float sq = v * v;
    #pragma unroll
    for (int off = 16; off; off >>= 1) sq += __shfl_xor_sync(0xffffffffu, sq, off);
    int f = row / N;
    float k = ks[f];
    float scale = 0.45f / (sqrtf(sq) * sqrtf(fabsf(k)));
    g_prod[row * D_IN + lane] = v * scale;
}

// ---------------- build x2 (random mapping), normalize, -> bf16 ---------------
__global__ void build_x2_kernel(const float* __restrict__ feat_free,
                                const float* __restrict__ ks,
                                const float* __restrict__ Ws,
                                const float* __restrict__ bias,
                                const float* __restrict__ W_free,
                                const float* __restrict__ b_free,
                                int N) {
    __shared__ float xi[4][D_IN];
    __shared__ float red[256];
    int n = blockIdx.x;
    int t = threadIdx.x;
    if (t < 96) {
        int f = t / 32, c = t % 32;
        xi[f][c] = g_prod[(f * N + n) * D_IN + c];
    } else if (t < 128) {
        xi[3][t - 96] = feat_free[n * D_IN + (t - 96)];
    }
    __syncthreads();

    int f = t >> 6;
    int col = t & 63;
    float z;
    if (f < 3) {
        float k = ks[f];
        float nsq = 0.f;
        #pragma unroll
        for (int c = 0; c < D_IN; c++) nsq += xi[f][c] * xi[f][c];
        float div = 0.f;
        const float* w = Ws + (f * DOUT + col) * D_IN;
        #pragma unroll
        for (int c = 0; c < D_IN; c++) {
            float dd = xi[f][c] - w[c];
            div += dd * dd;
        }
        float num = 1.f + k * nsq;
        float dist = logf(num / (div + EPS));
        z = expf(15.5f * dist) * cosf(dist + bias[f * DOUT + col]);
    } else {
        float dot = 0.f;
        const float* w = W_free + col * D_IN;
        #pragma unroll
        for (int c = 0; c < D_IN; c++) dot += xi[3][c] * w[c];
        z = expf(15.5f * dot) * cosf(dot + b_free[col]);
    }

    red[t] = z * z;
    __syncthreads();
    #pragma unroll
    for (int s = 128; s > 0; s >>= 1) {
        if (t < s) red[t] += red[t + s];
        __syncthreads();
    }
    float inv = rsqrtf(red[0]);
    g_xb[n * EMB + t] = __float2bfloat16(z * inv);
}

// ---------------- normalize x rows -> bf16 (+ zero accumulators) -------------
__global__ void norm_x_kernel(const float* __restrict__ x, int N) {
    __shared__ float red[256];
    int n = blockIdx.x;
    int t = threadIdx.x;
    if (t == 0) {
        g_rowsum[n] = 0.f;
        g_colsum[n] = 0.f;
        if (n == 0) g_macc = 0.0;
    }
    float v = x[n * EMB + t];
    red[t] = v * v;
    __syncthreads();
    #pragma unroll
    for (int s = 128; s > 0; s >>= 1) {
        if (t < s) red[t] += red[t + s];
        __syncthreads();
    }
    float inv = rsqrtf(red[0]);
    g_xa[n * EMB + t] = __float2bfloat16(v * inv);
}

// ---------------- sim GEMM: bf16 mma.sync, cp.async double-buffered ----------
// tile 128x128, BK=64, 2 stages, 2 CTAs/SM. 8 warps: warp_m in {0,1} (64 rows),
// warp_n in {0..3} (32 cols). warp tile = 4x4 of m16n8k16.
#define TILE 128
#define BK 64
#define RS 72                 // smem row stride in bf16 elems (144B, conflict-free)
#define MAT_BYTES (TILE * RS * 2)          // 18432
#define STAGE_BYTES (2 * MAT_BYTES)        // 36864
#define SIM_SMEM (2 * STAGE_BYTES)         // 73728

__global__ __launch_bounds__(256, 2) void sim_hmma_kernel(int N) {
    extern __shared__ char dynsm[];
    __shared__ float sRow[TILE];
    __shared__ float sCol[TILE];

    const uint32_t sbase = smem_u32(dynsm);
    const int t = threadIdx.x;
    const int lane = t & 31;
    const int wid = t >> 5;
    const int warp_m = wid & 1;
    const int warp_n = wid >> 1;
    const int g = lane >> 2;       // 0..7
    const int tig = lane & 3;      // 0..3
    const int i0 = blockIdx.y * TILE;
    const int j0 = blockIdx.x * TILE;

    // per-thread load coords: 4 chunks for A, 4 for B per stage
    // id = t + it*256 in [0,1024): row = id>>3 (0..127), ch = id&7 (16B chunk)
    const __nv_bfloat16* GA = g_xa;
    const __nv_bfloat16* GB = g_xb;

    // ---- prologue: stage 0
    {
        const int koff = 0;
        #pragma unroll
        for (int it = 0; it < 4; it++) {
            int id = t + it * 256;
            int row = id >> 3, ch = id & 7;
            cp_async16(sbase + row * 144 + ch * 16,
                       GA + (size_t)(i0 + row) * EMB + koff + ch * 8, i0 + row < N);
        }
        #pragma unroll
        for (int it = 0; it < 4; it++) {
            int id = t + it * 256;
            int row = id >> 3, ch = id & 7;
            cp_async16(sbase + MAT_BYTES + row * 144 + ch * 16,
                       GB + (size_t)(j0 + row) * EMB + koff + ch * 8, j0 + row < N);
        }
        CP_COMMIT();
    }

    float acc[4][4][4];
    #pragma unroll
    for (int mt = 0; mt < 4; mt++)
        #pragma unroll
        for (int nt = 0; nt < 4; nt++)
            #pragma unroll
            for (int c = 0; c < 4; c++) acc[mt][nt][c] = 0.f;

    // ldmatrix lane->address components
    const int aRow = lane & 15;
    const int aCol = (lane >> 4) * 8;
    const int bRow = (lane & 7) + ((lane >> 4) << 3);
    const int bCol = ((lane >> 3) & 1) * 8;

    #pragma unroll
    for (int s = 0; s < EMB / BK; s++) {
        // prefetch next stage
        if (s + 1 < EMB / BK) {
            uint32_t dst = sbase + ((s + 1) & 1) * STAGE_BYTES;
            const int koff = (s + 1) * BK;
            #pragma unroll
            for (int it = 0; it < 4; it++) {
                int id = t + it * 256;
                int row = id >> 3, ch = id & 7;
                cp_async16(dst + row * 144 + ch * 16,
                           GA + (size_t)(i0 + row) * EMB + koff + ch * 8, i0 + row < N);
            }
            #pragma unroll
            for (int it = 0; it < 4; it++) {
                int id = t + it * 256;
                int row = id >> 3, ch = id & 7;
                cp_async16(dst + MAT_BYTES + row * 144 + ch * 16,
                           GB + (size_t)(j0 + row) * EMB + koff + ch * 8, j0 + row < N);
            }
            CP_COMMIT();
            CP_WAIT(1);
        } else {
            CP_WAIT(0);
        }
        __syncthreads();

        const uint32_t aB = sbase + (s & 1) * STAGE_BYTES;
        const uint32_t bB = aB + MAT_BYTES;

        #pragma unroll
        for (int kk = 0; kk < BK / 16; kk++) {
            const int k0 = kk * 16;
            uint32_t a[4][4];
            #pragma unroll
            for (int mt = 0; mt < 4; mt++) {
                uint32_t addr = aB + ((warp_m * 64 + mt * 16 + aRow) * RS + k0 + aCol) * 2;
                asm volatile("ldmatrix.sync.aligned.m8n8.x4.shared.b16 {%0,%1,%2,%3}, [%4];"
                             : "=r"(a[mt][0]), "=r"(a[mt][1]), "=r"(a[mt][2]), "=r"(a[mt][3])
                             : "r"(addr));
            }
            uint32_t b[4][2];
            #pragma unroll
            for (int bq = 0; bq < 2; bq++) {
                uint32_t addr = bB + ((warp_n * 32 + bq * 16 + bRow) * RS + k0 + bCol) * 2;
                uint32_t r0, r1, r2, r3;
                asm volatile("ldmatrix.sync.aligned.m8n8.x4.shared.b16 {%0,%1,%2,%3}, [%4];"
                             : "=r"(r0), "=r"(r1), "=r"(r2), "=r"(r3)
                             : "r"(addr));
                b[bq * 2][0] = r0;     b[bq * 2][1] = r1;
                b[bq * 2 + 1][0] = r2; b[bq * 2 + 1][1] = r3;
            }
            #pragma unroll
            for (int mt = 0; mt < 4; mt++)
                #pragma unroll
                for (int nt = 0; nt < 4; nt++) {
                    asm volatile(
                        "mma.sync.aligned.m16n8k16.row.col.f32.bf16.bf16.f32 "
                        "{%0,%1,%2,%3}, {%4,%5,%6,%7}, {%8,%9}, {%0,%1,%2,%3};"
                        : "+f"(acc[mt][nt][0]), "+f"(acc[mt][nt][1]),
                          "+f"(acc[mt][nt][2]), "+f"(acc[mt][nt][3])
                        : "r"(a[mt][0]), "r"(a[mt][1]), "r"(a[mt][2]), "r"(a[mt][3]),
                          "r"(b[nt][0]), "r"(b[nt][1]));
                }
        }
        __syncthreads();
    }

    // ---- epilogue: exp2 + row/col/diag reductions -----------------------------
    if (t < TILE) { sRow[t] = 0.f; sCol[t] = 0.f; }
    __syncthreads();

    float rp[8];    // mt*2 + {lo,hi}
    float cp[8];    // nt*2 + parity
    #pragma unroll
    for (int r = 0; r < 8; r++) { rp[r] = 0.f; cp[r] = 0.f; }

    #pragma unroll
    for (int mt = 0; mt < 4; mt++) {
        int i_lo = i0 + warp_m * 64 + mt * 16 + g;
        int i_hi = i_lo + 8;
        #pragma unroll
        for (int nt = 0; nt < 4; nt++) {
            int j_e = j0 + warp_n * 32 + nt * 8 + 2 * tig;
            int j_o = j_e + 1;
            if (i_lo < N) {
                if (j_e < N) {
                    float e = exp2f(acc[mt][nt][0] * SIM_SCALE);
                    rp[mt * 2] += e; cp[nt * 2] += e;
                    if (i_lo == j_e) g_diag[i_lo] = e;
                }
                if (j_o < N) {
                    float e = exp2f(acc[mt][nt][1] * SIM_SCALE);
                    rp[mt * 2] += e; cp[nt * 2 + 1] += e;
                    if (i_lo == j_o) g_diag[i_lo] = e;
                }
            }
            if (i_hi < N) {
                if (j_e < N) {
                    float e = exp2f(acc[mt][nt][2] * SIM_SCALE);
                    rp[mt * 2 + 1] += e; cp[nt * 2] += e;
                    if (i_hi == j_e) g_diag[i_hi] = e;
                }
                if (j_o < N) {
                    float e = exp2f(acc[mt][nt][3] * SIM_SCALE);
                    rp[mt * 2 + 1] += e; cp[nt * 2 + 1] += e;
                    if (i_hi == j_o) g_diag[i_hi] = e;
                }
            }
        }
    }

    // rows: reduce across tig (lane bits 0-1)
    #pragma unroll
    for (int r = 0; r < 8; r++) {
        float v = rp[r];
        v += __shfl_xor_sync(0xffffffffu, v, 1);
        v += __shfl_xor_sync(0xffffffffu, v, 2);
        if (tig == 0) {
            int mt = r >> 1, h = r & 1;
            atomicAdd(&sRow[warp_m * 64 + mt * 16 + h * 8 + g], v);
        }
    }
    // cols: reduce across g (lane bits 2-4)
    #pragma unroll
    for (int c = 0; c < 8; c++) {
        float v = cp[c];
        v += __shfl_xor_sync(0xffffffffu, v, 4);
        v += __shfl_xor_sync(0xffffffffu, v, 8);
        v += __shfl_xor_sync(0xffffffffu, v, 16);
        if (g == 0) {
            int nt = c >> 1, par = c & 1;
            atomicAdd(&sCol[warp_n * 32 + nt * 8 + 2 * tig + par], v);
        }
    }
    __syncthreads();

    if (t < TILE) {
        int i = i0 + t;
        if (i < N) atomicAdd(&g_rowsum[i], sRow[t]);
        int j = j0 + t;
        if (j < N) atomicAdd(&g_colsum[j], sCol[t]);
    }
}

// ---------------- precompute H = product_p @ W1 (4 outputs/thread) -----------
__global__ void build_H_kernel(const float* __restrict__ feat_free,
                               const float* __restrict__ W1, int N) {
    int id = blockIdx.x * blockDim.x + threadIdx.x;
    int total = 4 * N * 48;
    if (id >= total) return;
    int p = id / (N * 48);
    int rem = id % (N * 48);
    int n = rem / 48;
    int jg = rem % 48;
    int part = jg >> 4;
    int jj = (jg & 15) * 4;
    const float* row = (p < 3) ? (g_prod + (p * N + n) * D_IN)
                               : (feat_free + n * D_IN);
    float4 s = make_float4(0.f, 0.f, 0.f, 0.f);
    #pragma unroll
    for (int cq = 0; cq < 8; cq++) {
        float4 rv = *(const float4*)(row + cq * 4);
        float rr[4] = {rv.x, rv.y, rv.z, rv.w};
        #pragma unroll
        for (int u = 0; u < 4; u++) {
            int c = cq * 4 + u;
            float4 w = *(const float4*)(W1 + (size_t)(part * 32 + c) * 64 + jj);
            s.x += rr[u] * w.x; s.y += rr[u] * w.y;
            s.z += rr[u] * w.z; s.w += rr[u] * w.w;
        }
    }
    *(float4*)(g_H + (size_t)(p * N + n) * 192 + part * 64 + jj) = s;
}

// ---------------- motif loss: warp per (product, sign, motif) ----------------
__global__ void motif_kernel(const int* __restrict__ motif,
                             const int* __restrict__ neg_uv,
                             const float* __restrict__ b1,
                             const float* __restrict__ W2,
                             const float* __restrict__ b2,
                             int N, int M) {
    __shared__ double sd[8];
    int gwarp = (blockIdx.x * blockDim.x + threadIdx.x) >> 5;
    int lane = threadIdx.x & 31;
    int wib = threadIdx.x >> 5;
    int total = 4 * 2 * M;
    double local = 0.0;

    if (gwarp < total) {
        int p = gwarp / (2 * M);
        int rem = gwarp % (2 * M);
        int s = rem / M;
        int m = rem % M;
        int u, v, w;
        if (s == 0) { u = motif[m];  v = motif[M + m];  w = motif[2 * M + m]; }
        else        { u = neg_uv[m]; v = neg_uv[M + m]; w = motif[2 * M + m]; }
        const float* base = g_H + (size_t)p * N * 192;
        float acc = 0.f;
        #pragma unroll
        for (int rep = 0; rep < 2; rep++) {
            int j = lane + rep * 32;
            float h = base[(size_t)u * 192 + j]
                    + base[(size_t)v * 192 + 64 + j]
                    + base[(size_t)w * 192 + 128 + j]
                    + b1[j];
            h = fmaxf(h, 0.f);
            acc += h * W2[j];
        }
        #pragma unroll
        for (int off = 16; off; off >>= 1) acc += __shfl_xor_sync(0xffffffffu, acc, off);
        if (lane == 0) {
            float logit = acc + b2[0];
            float z = s ? -logit : logit;
            float ls = fminf(z, 0.f) - log1pf(expf(-fabsf(z)));
            local = (double)ls;
        }
    }
    if (lane == 0) sd[wib] = local;
    __syncthreads();
    if (threadIdx.x == 0) {
        double sum = 0.0;
        #pragma unroll
        for (int i = 0; i < 8; i++) sum += sd[i];
        atomicAdd(&g_macc, sum);
    }
}

// ---------------- finalize ----------------------------------------------------
__global__ void finalize_kernel(float* __restrict__ out, int N, int M) {
    __shared__ double red[256];
    int t = threadIdx.x;
    double l = 0.0;
    for (int j = t; j < N; j += 256) {
        double pos = (double)g_diag[j];
        double lp = log(pos);
        l += (lp - log((double)g_colsum[j] - pos));
        l += (lp - log((double)g_rowsum[j] - pos));
    }
    red[t] = l;
    __syncthreads();
    #pragma unroll
    for (int s = 128; s > 0; s >>= 1) {
        if (t < s) red[t] += red[t + s];
        __syncthreads();
    }
    if (t == 0) {
        double cl = -0.5 * red[0] / (double)N;
        double motif_loss = -g_macc / (double)M;
        out[0] = (float)(cl + motif_loss);
    }
}

// ---------------- launch ------------------------------------------------------
extern "C" void kernel_launch(void* const* d_in, const int* in_sizes, int n_in,
                              void* d_out, int out_size) {
    const float* x         = (const float*)d_in[0];
    const float* feats     = (const float*)d_in[1];
    const float* feat_free = (const float*)d_in[2];
    const float* ks        = (const float*)d_in[3];
    const float* Ws        = (const float*)d_in[4];
    const float* bias      = (const float*)d_in[5];
    const float* W_free    = (const float*)d_in[6];
    const float* b_free    = (const float*)d_in[7];
    const float* W1        = (const float*)d_in[8];
    const float* b1        = (const float*)d_in[9];
    const float* W2        = (const float*)d_in[10];
    const float* b2        = (const float*)d_in[11];
    const int*   motif     = (const int*)d_in[12];
    const int*   neg_uv    = (const int*)d_in[13];
    float* out = (float*)d_out;

    int N = in_sizes[0] / EMB;        // 10000
    int M = in_sizes[12] / 3;         // 50000

    cudaFuncSetAttribute(sim_hmma_kernel,
                         cudaFuncAttributeMaxDynamicSharedMemorySize, SIM_SMEM);

    {
        int rows = 3 * N;
        int blocks = (rows * 32 + 255) / 256;
        norm_feats_kernel<<<blocks, 256>>>(feats, ks, N);
    }

    build_x2_kernel<<<N, 256>>>(feat_free, ks, Ws, bias, W_free, b_free, N);
    norm_x_kernel<<<N, 256>>>(x, N);          // also zeros rowsum/colsum/macc

    {
        dim3 grid((N + TILE - 1) / TILE, (N + TILE - 1) / TILE);
        sim_hmma_kernel<<<grid, 256, SIM_SMEM>>>(N);
    }

    {
        int total = 4 * N * 48;
        build_H_kernel<<<(total + 255) / 256, 256>>>(feat_free, W1, N);
        int warps = 4 * 2 * M;
        int blocks = (warps * 32 + 255) / 256;
        motif_kernel<<<blocks, 256>>>(motif, neg_uv, b1, W2, b2, N, M);
    }

    finalize_kernel<<<1, 256>>>(out, N, M);
}

// round 6
// speedup vs baseline: 3.0219x; 1.3671x over previous
#include <cuda_runtime.h>
#include <cuda_bf16.h>
#include <math.h>
#include <stdint.h>

// Problem-instance maxima (N=10000, M=50000, fixed shapes per reference)
#define NMAX 10016
#define D_IN 32
#define DOUT 64
#define EMB 256
#define EPS 1e-5f
// log2(e)/TEMP,  TEMP = 0.2
#define SIM_SCALE 7.2134752044448170f

// ---------------- scratch (static device globals; no allocation) -------------
__device__ float g_prod[3 * NMAX * D_IN];             // normalized riemannian feats
__device__ __nv_bfloat16 g_xa[NMAX * EMB];            // row-normalized x   (bf16)
__device__ __nv_bfloat16 g_xb[NMAX * EMB];            // row-normalized x2  (bf16)
__device__ float g_H[4 * NMAX * 192];                 // MLP layer-1 partials
__device__ float g_rowsum[NMAX];
__device__ float g_colsum[NMAX];
__device__ float g_diag[NMAX];
__device__ double g_macc;

__device__ __forceinline__ uint32_t smem_u32(const void* p) {
    uint32_t a;
    asm("{ .reg .u64 t; cvta.to.shared.u64 t, %1; cvt.u32.u64 %0, t; }" : "=r"(a) : "l"(p));
    return a;
}
__device__ __forceinline__ void cp_async16(uint32_t dst, const void* src, bool pred) {
    int sz = pred ? 16 : 0;
    asm volatile("cp.async.cg.shared.global [%0], [%1], 16, %2;"
                 :: "r"(dst), "l"(src), "r"(sz) : "memory");
}
#define CP_COMMIT() asm volatile("cp.async.commit_group;" ::: "memory")
#define CP_WAIT(n)  asm volatile("cp.async.wait_group %0;" :: "n"(n) : "memory")

// ---------------- normalize feats -> products --------------------------------
__global__ void norm_feats_kernel(const float* __restrict__ feats,
                                  const float* __restrict__ ks, int N) {
    int row = (blockIdx.x * blockDim.x + threadIdx.x) >> 5;
    int lane = threadIdx.x & 31;
    if (row >= 3 * N) return;
    float v = feats[row * D_IN + lane];
    float sq = v * v;
    #pragma unroll
    for (int off = 16; off; off >>= 1) sq += __shfl_xor_sync(0xffffffffu, sq, off);
    int f = row / N;
    float k = ks[f];
    float scale = 0.45f / (sqrtf(sq) * sqrtf(fabsf(k)));
    g_prod[row * D_IN + lane] = v * scale;
}

// ---------------- build x2 (random mapping), normalize, -> bf16 ---------------
// Weights cached in smem, transposed (stride 65: conflict-free reads).
// ||w|| = 1 (rows normalized in setup), so sum((xi-w)^2) = ||xi||^2 - 2 xi.w + 1.
__global__ __launch_bounds__(256) void build_x2_kernel(
        const float* __restrict__ feat_free,
        const float* __restrict__ ks,
        const float* __restrict__ Ws,
        const float* __restrict__ bias,
        const float* __restrict__ W_free,
        const float* __restrict__ b_free,
        int N) {
    __shared__ float ws[3 * 32 * 65];     // [f][c][col], c-stride 65
    __shared__ float wf[32 * 65];         // [c][col]
    __shared__ float xi[4 * D_IN];
    __shared__ float red[256];
    const int n = blockIdx.x;
    const int t = threadIdx.x;

    // cooperative transposed load of Ws (1536 float4) and W_free (512 float4)
    #pragma unroll
    for (int k = 0; k < 6; k++) {
        int idx4 = t + k * 256;
        float4 v = ((const float4*)Ws)[idx4];
        int row = idx4 >> 3;              // f*64 + col
        int c0 = (idx4 & 7) * 4;
        int f = row >> 6, col = row & 63;
        float* dst = ws + f * (32 * 65) + col;
        dst[(c0 + 0) * 65] = v.x; dst[(c0 + 1) * 65] = v.y;
        dst[(c0 + 2) * 65] = v.z; dst[(c0 + 3) * 65] = v.w;
    }
    #pragma unroll
    for (int k = 0; k < 2; k++) {
        int idx4 = t + k * 256;
        float4 v = ((const float4*)W_free)[idx4];
        int col = idx4 >> 3;
        int c0 = (idx4 & 7) * 4;
        float* dst = wf + col;
        dst[(c0 + 0) * 65] = v.x; dst[(c0 + 1) * 65] = v.y;
        dst[(c0 + 2) * 65] = v.z; dst[(c0 + 3) * 65] = v.w;
    }
    if (t < 96) {
        xi[t] = g_prod[((t >> 5) * N + n) * D_IN + (t & 31)];
    } else if (t < 128) {
        xi[t] = feat_free[n * D_IN + (t - 96)];
    }
    __syncthreads();

    const int f = t >> 6;
    const int col = t & 63;
    float z;
    if (f < 3) {
        const float* xv = xi + f * D_IN;
        const float* wv = ws + f * (32 * 65) + col;
        float nsq = 0.f, dot = 0.f;
        #pragma unroll
        for (int c = 0; c < D_IN; c++) {
            float xc = xv[c];
            nsq += xc * xc;
            dot += xc * wv[c * 65];
        }
        float k = ks[f];
        float div = nsq - 2.f * dot + 1.f;
        float num = 1.f + k * nsq;
        float dist = logf(num / (div + EPS));
        z = expf(15.5f * dist) * cosf(dist + bias[f * DOUT + col]);
    } else {
        const float* xv = xi + 3 * D_IN;
        const float* wv = wf + col;
        float dot = 0.f;
        #pragma unroll
        for (int c = 0; c < D_IN; c++) dot += xv[c] * wv[c * 65];
        z = expf(15.5f * dot) * cosf(dot + b_free[col]);
    }

    red[t] = z * z;
    __syncthreads();
    #pragma unroll
    for (int s = 128; s > 0; s >>= 1) {
        if (t < s) red[t] += red[t + s];
        __syncthreads();
    }
    float inv = rsqrtf(red[0]);
    g_xb[n * EMB + t] = __float2bfloat16(z * inv);
}

// ---------------- normalize x rows -> bf16 (+ zero accumulators) -------------
__global__ void norm_x_kernel(const float* __restrict__ x, int N) {
    __shared__ float red[256];
    int n = blockIdx.x;
    int t = threadIdx.x;
    if (t == 0) {
        g_rowsum[n] = 0.f;
        g_colsum[n] = 0.f;
        if (n == 0) g_macc = 0.0;
    }
    float v = x[n * EMB + t];
    red[t] = v * v;
    __syncthreads();
    #pragma unroll
    for (int s = 128; s > 0; s >>= 1) {
        if (t < s) red[t] += red[t + s];
        __syncthreads();
    }
    float inv = rsqrtf(red[0]);
    g_xa[n * EMB + t] = __float2bfloat16(v * inv);
}

// ---------------- sim GEMM: bf16 mma.sync, cp.async double-buffered ----------
#define TILE 128
#define BK 64
#define RS 72                 // smem row stride in bf16 elems (144B, conflict-free)
#define MAT_BYTES (TILE * RS * 2)          // 18432
#define STAGE_BYTES (2 * MAT_BYTES)        // 36864
#define SIM_SMEM (2 * STAGE_BYTES)         // 73728

__global__ __launch_bounds__(256, 2) void sim_hmma_kernel(int N) {
    extern __shared__ char dynsm[];
    __shared__ float sRow[TILE];
    __shared__ float sCol[TILE];

    const uint32_t sbase = smem_u32(dynsm);
    const int t = threadIdx.x;
    const int lane = t & 31;
    const int wid = t >> 5;
    const int warp_m = wid & 1;
    const int warp_n = wid >> 1;
    const int g = lane >> 2;       // 0..7
    const int tig = lane & 3;      // 0..3
    const int i0 = blockIdx.y * TILE;
    const int j0 = blockIdx.x * TILE;

    const __nv_bfloat16* GA = g_xa;
    const __nv_bfloat16* GB = g_xb;

    // ---- prologue: stage 0
    {
        const int koff = 0;
        #pragma unroll
        for (int it = 0; it < 4; it++) {
            int id = t + it * 256;
            int row = id >> 3, ch = id & 7;
            cp_async16(sbase + row * 144 + ch * 16,
                       GA + (size_t)(i0 + row) * EMB + koff + ch * 8, i0 + row < N);
        }
        #pragma unroll
        for (int it = 0; it < 4; it++) {
            int id = t + it * 256;
            int row = id >> 3, ch = id & 7;
            cp_async16(sbase + MAT_BYTES + row * 144 + ch * 16,
                       GB + (size_t)(j0 + row) * EMB + koff + ch * 8, j0 + row < N);
        }
        CP_COMMIT();
    }

    float acc[4][4][4];
    #pragma unroll
    for (int mt = 0; mt < 4; mt++)
        #pragma unroll
        for (int nt = 0; nt < 4; nt++)
            #pragma unroll
            for (int c = 0; c < 4; c++) acc[mt][nt][c] = 0.f;

    const int aRow = lane & 15;
    const int aCol = (lane >> 4) * 8;
    const int bRow = (lane & 7) + ((lane >> 4) << 3);
    const int bCol = ((lane >> 3) & 1) * 8;

    #pragma unroll
    for (int s = 0; s < EMB / BK; s++) {
        if (s + 1 < EMB / BK) {
            uint32_t dst = sbase + ((s + 1) & 1) * STAGE_BYTES;
            const int koff = (s + 1) * BK;
            #pragma unroll
            for (int it = 0; it < 4; it++) {
                int id = t + it * 256;
                int row = id >> 3, ch = id & 7;
                cp_async16(dst + row * 144 + ch * 16,
                           GA + (size_t)(i0 + row) * EMB + koff + ch * 8, i0 + row < N);
            }
            #pragma unroll
            for (int it = 0; it < 4; it++) {
                int id = t + it * 256;
                int row = id >> 3, ch = id & 7;
                cp_async16(dst + MAT_BYTES + row * 144 + ch * 16,
                           GB + (size_t)(j0 + row) * EMB + koff + ch * 8, j0 + row < N);
            }
            CP_COMMIT();
            CP_WAIT(1);
        } else {
            CP_WAIT(0);
        }
        __syncthreads();

        const uint32_t aB = sbase + (s & 1) * STAGE_BYTES;
        const uint32_t bB = aB + MAT_BYTES;

        #pragma unroll
        for (int kk = 0; kk < BK / 16; kk++) {
            const int k0 = kk * 16;
            uint32_t a[4][4];
            #pragma unroll
            for (int mt = 0; mt < 4; mt++) {
                uint32_t addr = aB + ((warp_m * 64 + mt * 16 + aRow) * RS + k0 + aCol) * 2;
                asm volatile("ldmatrix.sync.aligned.m8n8.x4.shared.b16 {%0,%1,%2,%3}, [%4];"
                             : "=r"(a[mt][0]), "=r"(a[mt][1]), "=r"(a[mt][2]), "=r"(a[mt][3])
                             : "r"(addr));
            }
            uint32_t b[4][2];
            #pragma unroll
            for (int bq = 0; bq < 2; bq++) {
                uint32_t addr = bB + ((warp_n * 32 + bq * 16 + bRow) * RS + k0 + bCol) * 2;
                uint32_t r0, r1, r2, r3;
                asm volatile("ldmatrix.sync.aligned.m8n8.x4.shared.b16 {%0,%1,%2,%3}, [%4];"
                             : "=r"(r0), "=r"(r1), "=r"(r2), "=r"(r3)
                             : "r"(addr));
                b[bq * 2][0] = r0;     b[bq * 2][1] = r1;
                b[bq * 2 + 1][0] = r2; b[bq * 2 + 1][1] = r3;
            }
            #pragma unroll
            for (int mt = 0; mt < 4; mt++)
                #pragma unroll
                for (int nt = 0; nt < 4; nt++) {
                    asm volatile(
                        "mma.sync.aligned.m16n8k16.row.col.f32.bf16.bf16.f32 "
                        "{%0,%1,%2,%3}, {%4,%5,%6,%7}, {%8,%9}, {%0,%1,%2,%3};"
                        : "+f"(acc[mt][nt][0]), "+f"(acc[mt][nt][1]),
                          "+f"(acc[mt][nt][2]), "+f"(acc[mt][nt][3])
                        : "r"(a[mt][0]), "r"(a[mt][1]), "r"(a[mt][2]), "r"(a[mt][3]),
                          "r"(b[nt][0]), "r"(b[nt][1]));
                }
        }
        __syncthreads();
    }

    // ---- epilogue: exp2 + row/col/diag reductions -----------------------------
    if (t < TILE) { sRow[t] = 0.f; sCol[t] = 0.f; }
    __syncthreads();

    float rp[8];
    float cp[8];
    #pragma unroll
    for (int r = 0; r < 8; r++) { rp[r] = 0.f; cp[r] = 0.f; }

    #pragma unroll
    for (int mt = 0; mt < 4; mt++) {
        int i_lo = i0 + warp_m * 64 + mt * 16 + g;
        int i_hi = i_lo + 8;
        #pragma unroll
        for (int nt = 0; nt < 4; nt++) {
            int j_e = j0 + warp_n * 32 + nt * 8 + 2 * tig;
            int j_o = j_e + 1;
            if (i_lo < N) {
                if (j_e < N) {
                    float e = exp2f(acc[mt][nt][0] * SIM_SCALE);
                    rp[mt * 2] += e; cp[nt * 2] += e;
                    if (i_lo == j_e) g_diag[i_lo] = e;
                }
                if (j_o < N) {
                    float e = exp2f(acc[mt][nt][1] * SIM_SCALE);
                    rp[mt * 2] += e; cp[nt * 2 + 1] += e;
                    if (i_lo == j_o) g_diag[i_lo] = e;
                }
            }
            if (i_hi < N) {
                if (j_e < N) {
                    float e = exp2f(acc[mt][nt][2] * SIM_SCALE);
                    rp[mt * 2 + 1] += e; cp[nt * 2] += e;
                    if (i_hi == j_e) g_diag[i_hi] = e;
                }
                if (j_o < N) {
                    float e = exp2f(acc[mt][nt][3] * SIM_SCALE);
                    rp[mt * 2 + 1] += e; cp[nt * 2 + 1] += e;
                    if (i_hi == j_o) g_diag[i_hi] = e;
                }
            }
        }
    }

    #pragma unroll
    for (int r = 0; r < 8; r++) {
        float v = rp[r];
        v += __shfl_xor_sync(0xffffffffu, v, 1);
        v += __shfl_xor_sync(0xffffffffu, v, 2);
        if (tig == 0) {
            int mt = r >> 1, h = r & 1;
            atomicAdd(&sRow[warp_m * 64 + mt * 16 + h * 8 + g], v);
        }
    }
    #pragma unroll
    for (int c = 0; c < 8; c++) {
        float v = cp[c];
        v += __shfl_xor_sync(0xffffffffu, v, 4);
        v += __shfl_xor_sync(0xffffffffu, v, 8);
        v += __shfl_xor_sync(0xffffffffu, v, 16);
        if (g == 0) {
            int nt = c >> 1, par = c & 1;
            atomicAdd(&sCol[warp_n * 32 + nt * 8 + 2 * tig + par], v);
        }
    }
    __syncthreads();

    if (t < TILE) {
        int i = i0 + t;
        if (i < N) atomicAdd(&g_rowsum[i], sRow[t]);
        int j = j0 + t;
        if (j < N) atomicAdd(&g_colsum[j], sCol[t]);
    }
}

// ---------------- precompute H = product_p @ W1 (4 outputs/thread) -----------
__global__ void build_H_kernel(const float* __restrict__ feat_free,
                               const float* __restrict__ W1, int N) {
    int id = blockIdx.x * blockDim.x + threadIdx.x;
    int total = 4 * N * 48;
    if (id >= total) return;
    int p = id / (N * 48);
    int rem = id % (N * 48);
    int n = rem / 48;
    int jg = rem % 48;
    int part = jg >> 4;
    int jj = (jg & 15) * 4;
    const float* row = (p < 3) ? (g_prod + (p * N + n) * D_IN)
                               : (feat_free + n * D_IN);
    float4 s = make_float4(0.f, 0.f, 0.f, 0.f);
    #pragma unroll
    for (int cq = 0; cq < 8; cq++) {
        float4 rv = *(const float4*)(row + cq * 4);
        float rr[4] = {rv.x, rv.y, rv.z, rv.w};
        #pragma unroll
        for (int u = 0; u < 4; u++) {
            int c = cq * 4 + u;
            float4 w = *(const float4*)(W1 + (size_t)(part * 32 + c) * 64 + jj);
            s.x += rr[u] * w.x; s.y += rr[u] * w.y;
            s.z += rr[u] * w.z; s.w += rr[u] * w.w;
        }
    }
    *(float4*)(g_H + (size_t)(p * N + n) * 192 + part * 64 + jj) = s;
}

// ---------------- motif loss: warp per (product, sign, motif) ----------------
__global__ void motif_kernel(const int* __restrict__ motif,
                             const int* __restrict__ neg_uv,
                             const float* __restrict__ b1,
                             const float* __restrict__ W2,
                             const float* __restrict__ b2,
                             int N, int M) {
    __shared__ double sd[8];
    int gwarp = (blockIdx.x * blockDim.x + threadIdx.x) >> 5;
    int lane = threadIdx.x & 31;
    int wib = threadIdx.x >> 5;
    int total = 4 * 2 * M;
    double local = 0.0;

    if (gwarp < total) {
        int p = gwarp / (2 * M);
        int rem = gwarp % (2 * M);
        int s = rem / M;
        int m = rem % M;
        int u, v, w;
        if (s == 0) { u = motif[m];  v = motif[M + m];  w = motif[2 * M + m]; }
        else        { u = neg_uv[m]; v = neg_uv[M + m]; w = motif[2 * M + m]; }
        const float* base = g_H + (size_t)p * N * 192;
        float acc = 0.f;
        #pragma unroll
        for (int rep = 0; rep < 2; rep++) {
            int j = lane + rep * 32;
            float h = base[(size_t)u * 192 + j]
                    + base[(size_t)v * 192 + 64 + j]
                    + base[(size_t)w * 192 + 128 + j]
                    + b1[j];
            h = fmaxf(h, 0.f);
            acc += h * W2[j];
        }
        #pragma unroll
        for (int off = 16; off; off >>= 1) acc += __shfl_xor_sync(0xffffffffu, acc, off);
        if (lane == 0) {
            float logit = acc + b2[0];
            float z = s ? -logit : logit;
            float ls = fminf(z, 0.f) - log1pf(expf(-fabsf(z)));
            local = (double)ls;
        }
    }
    if (lane == 0) sd[wib] = local;
    __syncthreads();
    if (threadIdx.x == 0) {
        double sum = 0.0;
        #pragma unroll
        for (int i = 0; i < 8; i++) sum += sd[i];
        atomicAdd(&g_macc, sum);
    }
}

// ---------------- finalize ----------------------------------------------------
__global__ void finalize_kernel(float* __restrict__ out, int N, int M) {
    __shared__ double red[256];
    int t = threadIdx.x;
    double l = 0.0;
    for (int j = t; j < N; j += 256) {
        double pos = (double)g_diag[j];
        double lp = log(pos);
        l += (lp - log((double)g_colsum[j] - pos));
        l += (lp - log((double)g_rowsum[j] - pos));
    }
    red[t] = l;
    __syncthreads();
    #pragma unroll
    for (int s = 128; s > 0; s >>= 1) {
        if (t < s) red[t] += red[t + s];
        __syncthreads();
    }
    if (t == 0) {
        double cl = -0.5 * red[0] / (double)N;
        double motif_loss = -g_macc / (double)M;
        out[0] = (float)(cl + motif_loss);
    }
}

// ---------------- launch ------------------------------------------------------
extern "C" void kernel_launch(void* const* d_in, const int* in_sizes, int n_in,
                              void* d_out, int out_size) {
    const float* x         = (const float*)d_in[0];
    const float* feats     = (const float*)d_in[1];
    const float* feat_free = (const float*)d_in[2];
    const float* ks        = (const float*)d_in[3];
    const float* Ws        = (const float*)d_in[4];
    const float* bias      = (const float*)d_in[5];
    const float* W_free    = (const float*)d_in[6];
    const float* b_free    = (const float*)d_in[7];
    const float* W1        = (const float*)d_in[8];
    const float* b1        = (const float*)d_in[9];
    const float* W2        = (const float*)d_in[10];
    const float* b2        = (const float*)d_in[11];
    const int*   motif     = (const int*)d_in[12];
    const int*   neg_uv    = (const int*)d_in[13];
    float* out = (float*)d_out;

    int N = in_sizes[0] / EMB;        // 10000
    int M = in_sizes[12] / 3;         // 50000

    cudaFuncSetAttribute(sim_hmma_kernel,
                         cudaFuncAttributeMaxDynamicSharedMemorySize, SIM_SMEM);

    {
        int rows = 3 * N;
        int blocks = (rows * 32 + 255) / 256;
        norm_feats_kernel<<<blocks, 256>>>(feats, ks, N);
    }

    build_x2_kernel<<<N, 256>>>(feat_free, ks, Ws, bias, W_free, b_free, N);
    norm_x_kernel<<<N, 256>>>(x, N);          // also zeros rowsum/colsum/macc

    {
        dim3 grid((N + TILE - 1) / TILE, (N + TILE - 1) / TILE);
        sim_hmma_kernel<<<grid, 256, SIM_SMEM>>>(N);
    }

    {
        int total = 4 * N * 48;
        build_H_kernel<<<(total + 255) / 256, 256>>>(feat_free, W1, N);
        int warps = 4 * 2 * M;
        int blocks = (warps * 32 + 255) / 256;
        motif_kernel<<<blocks, 256>>>(motif, neg_uv, b1, W2, b2, N, M);
    }

    finalize_kernel<<<1, 256>>>(out, N, M);
}

// round 7
// speedup vs baseline: 5.4471x; 1.8025x over previous
#include <cuda_runtime.h>
#include <cuda_bf16.h>
#include <math.h>
#include <stdint.h>

// Problem-instance maxima (N=10000, M=50000, fixed shapes per reference)
#define NMAX 10016
#define D_IN 32
#define DOUT 64
#define EMB 256
#define EPS 1e-5f
// log2(e)/TEMP,  TEMP = 0.2
#define SIM_SCALE 7.2134752044448170f

// ---------------- scratch (static device globals; no allocation) -------------
__device__ float g_prod[3 * NMAX * D_IN];             // normalized riemannian feats
__device__ __nv_bfloat16 g_xa[NMAX * EMB];            // row-normalized x   (bf16)
__device__ __nv_bfloat16 g_xb[NMAX * EMB];            // row-normalized x2  (bf16)
__device__ float g_H[4 * NMAX * 192];                 // MLP layer-1 partials
__device__ float g_rowsum[NMAX];
__device__ float g_colsum[NMAX];
__device__ float g_diag[NMAX];
__device__ double g_macc;                             // motif log-sigmoid sum
__device__ double g_clacc;                            // contrastive log-ratio sum

__device__ __forceinline__ uint32_t smem_u32(const void* p) {
    uint32_t a;
    asm("{ .reg .u64 t; cvta.to.shared.u64 t, %1; cvt.u32.u64 %0, t; }" : "=r"(a) : "l"(p));
    return a;
}
__device__ __forceinline__ void cp_async16(uint32_t dst, const void* src, bool pred) {
    int sz = pred ? 16 : 0;
    asm volatile("cp.async.cg.shared.global [%0], [%1], 16, %2;"
                 :: "r"(dst), "l"(src), "r"(sz) : "memory");
}
#define CP_COMMIT() asm volatile("cp.async.commit_group;" ::: "memory")
#define CP_WAIT(n)  asm volatile("cp.async.wait_group %0;" :: "n"(n) : "memory")

// ---------------- normalize feats -> products --------------------------------
__global__ void norm_feats_kernel(const float* __restrict__ feats,
                                  const float* __restrict__ ks, int N) {
    int row = (blockIdx.x * blockDim.x + threadIdx.x) >> 5;
    int lane = threadIdx.x & 31;
    if (row >= 3 * N) return;
    float v = feats[row * D_IN + lane];
    float sq = v * v;
    #pragma unroll
    for (int off = 16; off; off >>= 1) sq += __shfl_xor_sync(0xffffffffu, sq, off);
    int f = row / N;
    float k = ks[f];
    float scale = 0.45f / (sqrtf(sq) * sqrtf(fabsf(k)));
    g_prod[row * D_IN + lane] = v * scale;
}

// ---------------- normalize x rows -> bf16 (+ zero accumulators) -------------
__global__ void norm_x_kernel(const float* __restrict__ x, int N) {
    __shared__ float red[256];
    int n = blockIdx.x;
    int t = threadIdx.x;
    if (t == 0) {
        g_rowsum[n] = 0.f;
        g_colsum[n] = 0.f;
        if (n == 0) { g_macc = 0.0; g_clacc = 0.0; }
    }
    float v = x[n * EMB + t];
    red[t] = v * v;
    __syncthreads();
    #pragma unroll
    for (int s = 128; s > 0; s >>= 1) {
        if (t < s) red[t] += red[t + s];
        __syncthreads();
    }
    float inv = rsqrtf(red[0]);
    g_xa[n * EMB + t] = __float2bfloat16(v * inv);
}

// ---------------- precompute H = product_p @ W1 (4 outputs/thread) -----------
__global__ void build_H_kernel(const float* __restrict__ feat_free,
                               const float* __restrict__ W1, int N) {
    int id = blockIdx.x * blockDim.x + threadIdx.x;
    int total = 4 * N * 48;
    if (id >= total) return;
    int p = id / (N * 48);
    int rem = id % (N * 48);
    int n = rem / 48;
    int jg = rem % 48;
    int part = jg >> 4;
    int jj = (jg & 15) * 4;
    const float* row = (p < 3) ? (g_prod + (p * N + n) * D_IN)
                               : (feat_free + n * D_IN);
    float4 s = make_float4(0.f, 0.f, 0.f, 0.f);
    #pragma unroll
    for (int cq = 0; cq < 8; cq++) {
        float4 rv = *(const float4*)(row + cq * 4);
        float rr[4] = {rv.x, rv.y, rv.z, rv.w};
        #pragma unroll
        for (int u = 0; u < 4; u++) {
            int c = cq * 4 + u;
            float4 w = *(const float4*)(W1 + (size_t)(part * 32 + c) * 64 + jj);
            s.x += rr[u] * w.x; s.y += rr[u] * w.y;
            s.z += rr[u] * w.z; s.w += rr[u] * w.w;
        }
    }
    *(float4*)(g_H + (size_t)(p * N + n) * 192 + part * 64 + jj) = s;
}

// ---------------- build x2 (random mapping), normalize, -> bf16 ---------------
// 8 rows per block; weights cached in smem (transposed, stride 65).
// ||w|| = 1, so sum((xi-w)^2) = ||xi||^2 - 2 xi.w + 1.
#define X2_ROWS 8
__global__ __launch_bounds__(256) void build_x2_kernel(
        const float* __restrict__ feat_free,
        const float* __restrict__ ks,
        const float* __restrict__ Ws,
        const float* __restrict__ bias,
        const float* __restrict__ W_free,
        const float* __restrict__ b_free,
        int N) {
    __shared__ float ws[3 * 32 * 65];     // [f][c][col], c-stride 65
    __shared__ float wf[32 * 65];         // [c][col]
    __shared__ float xi[X2_ROWS][128];
    __shared__ float red[X2_ROWS][256];
    const int n0 = blockIdx.x * X2_ROWS;
    const int t = threadIdx.x;

    // cooperative transposed load of Ws (1536 float4) and W_free (512 float4)
    #pragma unroll
    for (int k = 0; k < 6; k++) {
        int idx4 = t + k * 256;
        float4 v = ((const float4*)Ws)[idx4];
        int row = idx4 >> 3;              // f*64 + col
        int c0 = (idx4 & 7) * 4;
        int f = row >> 6, col = row & 63;
        float* dst = ws + f * (32 * 65) + col;
        dst[(c0 + 0) * 65] = v.x; dst[(c0 + 1) * 65] = v.y;
        dst[(c0 + 2) * 65] = v.z; dst[(c0 + 3) * 65] = v.w;
    }
    #pragma unroll
    for (int k = 0; k < 2; k++) {
        int idx4 = t + k * 256;
        float4 v = ((const float4*)W_free)[idx4];
        int col = idx4 >> 3;
        int c0 = (idx4 & 7) * 4;
        float* dst = wf + col;
        dst[(c0 + 0) * 65] = v.x; dst[(c0 + 1) * 65] = v.y;
        dst[(c0 + 2) * 65] = v.z; dst[(c0 + 3) * 65] = v.w;
    }
    // load xi for 8 rows (1024 values, 4 per thread)
    #pragma unroll
    for (int rr = 0; rr < 4; rr++) {
        int idx = t + rr * 256;
        int r = idx >> 7;                 // row 0..7
        int c = idx & 127;
        int n = n0 + r;
        float v;
        if (n < N) {
            v = (c < 96) ? g_prod[((c >> 5) * N + n) * D_IN + (c & 31)]
                         : feat_free[n * D_IN + (c - 96)];
        } else v = 1.f;                   // dummy (avoids div-by-0 in norm)
        xi[r][c] = v;
    }
    __syncthreads();

    const int f = t >> 6;
    const int col = t & 63;
    const float kf = (f < 3) ? ks[f] : 0.f;
    const float bv = (f < 3) ? bias[f * DOUT + col] : b_free[col];

    float z[X2_ROWS];
    #pragma unroll
    for (int r = 0; r < X2_ROWS; r++) {
        float zv;
        if (f < 3) {
            const float* xv = xi[r] + f * D_IN;
            const float* wv = ws + f * (32 * 65) + col;
            float nsq = 0.f, dot = 0.f;
            #pragma unroll
            for (int c = 0; c < D_IN; c++) {
                float xc = xv[c];
                nsq += xc * xc;
                dot += xc * wv[c * 65];
            }
            float div = nsq - 2.f * dot + 1.f;
            float num = 1.f + kf * nsq;
            float dist = logf(num / (div + EPS));
            zv = expf(15.5f * dist) * cosf(dist + bv);
        } else {
            const float* xv = xi[r] + 3 * D_IN;
            const float* wv = wf + col;
            float dot = 0.f;
            #pragma unroll
            for (int c = 0; c < D_IN; c++) dot += xv[c] * wv[c * 65];
            zv = expf(15.5f * dot) * cosf(dot + bv);
        }
        z[r] = zv;
        red[r][t] = zv * zv;
    }
    __syncthreads();
    #pragma unroll
    for (int s = 128; s > 0; s >>= 1) {
        if (t < s) {
            #pragma unroll
            for (int r = 0; r < X2_ROWS; r++) red[r][t] += red[r][t + s];
        }
        __syncthreads();
    }
    #pragma unroll
    for (int r = 0; r < X2_ROWS; r++) {
        int n = n0 + r;
        if (n < N) {
            float inv = rsqrtf(red[r][0]);
            g_xb[n * EMB + t] = __float2bfloat16(z[r] * inv);
        }
    }
}

// ---------------- sim GEMM: bf16 mma.sync, cp.async double-buffered ----------
#define TILE 128
#define BK 64
#define RS 72                 // smem row stride in bf16 elems (144B, conflict-free)
#define MAT_BYTES (TILE * RS * 2)          // 18432
#define STAGE_BYTES (2 * MAT_BYTES)        // 36864
#define SIM_SMEM (2 * STAGE_BYTES)         // 73728

__global__ __launch_bounds__(256, 2) void sim_hmma_kernel(int N) {
    extern __shared__ char dynsm[];
    __shared__ float sRow[TILE];
    __shared__ float sCol[TILE];

    const uint32_t sbase = smem_u32(dynsm);
    const int t = threadIdx.x;
    const int lane = t & 31;
    const int wid = t >> 5;
    const int warp_m = wid & 1;
    const int warp_n = wid >> 1;
    const int g = lane >> 2;       // 0..7
    const int tig = lane & 3;      // 0..3
    const int i0 = blockIdx.y * TILE;
    const int j0 = blockIdx.x * TILE;

    const __nv_bfloat16* GA = g_xa;
    const __nv_bfloat16* GB = g_xb;

    // ---- prologue: stage 0
    {
        const int koff = 0;
        #pragma unroll
        for (int it = 0; it < 4; it++) {
            int id = t + it * 256;
            int row = id >> 3, ch = id & 7;
            cp_async16(sbase + row * 144 + ch * 16,
                       GA + (size_t)(i0 + row) * EMB + koff + ch * 8, i0 + row < N);
        }
        #pragma unroll
        for (int it = 0; it < 4; it++) {
            int id = t + it * 256;
            int row = id >> 3, ch = id & 7;
            cp_async16(sbase + MAT_BYTES + row * 144 + ch * 16,
                       GB + (size_t)(j0 + row) * EMB + koff + ch * 8, j0 + row < N);
        }
        CP_COMMIT();
    }

    float acc[4][4][4];
    #pragma unroll
    for (int mt = 0; mt < 4; mt++)
        #pragma unroll
        for (int nt = 0; nt < 4; nt++)
            #pragma unroll
            for (int c = 0; c < 4; c++) acc[mt][nt][c] = 0.f;

    const int aRow = lane & 15;
    const int aCol = (lane >> 4) * 8;
    const int bRow = (lane & 7) + ((lane >> 4) << 3);
    const int bCol = ((lane >> 3) & 1) * 8;

    #pragma unroll
    for (int s = 0; s < EMB / BK; s++) {
        if (s + 1 < EMB / BK) {
            uint32_t dst = sbase + ((s + 1) & 1) * STAGE_BYTES;
            const int koff = (s + 1) * BK;
            #pragma unroll
            for (int it = 0; it < 4; it++) {
                int id = t + it * 256;
                int row = id >> 3, ch = id & 7;
                cp_async16(dst + row * 144 + ch * 16,
                           GA + (size_t)(i0 + row) * EMB + koff + ch * 8, i0 + row < N);
            }
            #pragma unroll
            for (int it = 0; it < 4; it++) {
                int id = t + it * 256;
                int row = id >> 3, ch = id & 7;
                cp_async16(dst + MAT_BYTES + row * 144 + ch * 16,
                           GB + (size_t)(j0 + row) * EMB + koff + ch * 8, j0 + row < N);
            }
            CP_COMMIT();
            CP_WAIT(1);
        } else {
            CP_WAIT(0);
        }
        __syncthreads();

        const uint32_t aB = sbase + (s & 1) * STAGE_BYTES;
        const uint32_t bB = aB + MAT_BYTES;

        #pragma unroll
        for (int kk = 0; kk < BK / 16; kk++) {
            const int k0 = kk * 16;
            uint32_t a[4][4];
            #pragma unroll
            for (int mt = 0; mt < 4; mt++) {
                uint32_t addr = aB + ((warp_m * 64 + mt * 16 + aRow) * RS + k0 + aCol) * 2;
                asm volatile("ldmatrix.sync.aligned.m8n8.x4.shared.b16 {%0,%1,%2,%3}, [%4];"
                             : "=r"(a[mt][0]), "=r"(a[mt][1]), "=r"(a[mt][2]), "=r"(a[mt][3])
                             : "r"(addr));
            }
            uint32_t b[4][2];
            #pragma unroll
            for (int bq = 0; bq < 2; bq++) {
                uint32_t addr = bB + ((warp_n * 32 + bq * 16 + bRow) * RS + k0 + bCol) * 2;
                uint32_t r0, r1, r2, r3;
                asm volatile("ldmatrix.sync.aligned.m8n8.x4.shared.b16 {%0,%1,%2,%3}, [%4];"
                             : "=r"(r0), "=r"(r1), "=r"(r2), "=r"(r3)
                             : "r"(addr));
                b[bq * 2][0] = r0;     b[bq * 2][1] = r1;
                b[bq * 2 + 1][0] = r2; b[bq * 2 + 1][1] = r3;
            }
            #pragma unroll
            for (int mt = 0; mt < 4; mt++)
                #pragma unroll
                for (int nt = 0; nt < 4; nt++) {
                    asm volatile(
                        "mma.sync.aligned.m16n8k16.row.col.f32.bf16.bf16.f32 "
                        "{%0,%1,%2,%3}, {%4,%5,%6,%7}, {%8,%9}, {%0,%1,%2,%3};"
                        : "+f"(acc[mt][nt][0]), "+f"(acc[mt][nt][1]),
                          "+f"(acc[mt][nt][2]), "+f"(acc[mt][nt][3])
                        : "r"(a[mt][0]), "r"(a[mt][1]), "r"(a[mt][2]), "r"(a[mt][3]),
                          "r"(b[nt][0]), "r"(b[nt][1]));
                }
        }
        __syncthreads();
    }

    // ---- epilogue: exp2 + row/col/diag reductions -----------------------------
    if (t < TILE) { sRow[t] = 0.f; sCol[t] = 0.f; }
    __syncthreads();

    float rp[8];
    float cp[8];
    #pragma unroll
    for (int r = 0; r < 8; r++) { rp[r] = 0.f; cp[r] = 0.f; }

    #pragma unroll
    for (int mt = 0; mt < 4; mt++) {
        int i_lo = i0 + warp_m * 64 + mt * 16 + g;
        int i_hi = i_lo + 8;
        #pragma unroll
        for (int nt = 0; nt < 4; nt++) {
            int j_e = j0 + warp_n * 32 + nt * 8 + 2 * tig;
            int j_o = j_e + 1;
            if (i_lo < N) {
                if (j_e < N) {
                    float e = exp2f(acc[mt][nt][0] * SIM_SCALE);
                    rp[mt * 2] += e; cp[nt * 2] += e;
                    if (i_lo == j_e) g_diag[i_lo] = e;
                }
                if (j_o < N) {
                    float e = exp2f(acc[mt][nt][1] * SIM_SCALE);
                    rp[mt * 2] += e; cp[nt * 2 + 1] += e;
                    if (i_lo == j_o) g_diag[i_lo] = e;
                }
            }
            if (i_hi < N) {
                if (j_e < N) {
                    float e = exp2f(acc[mt][nt][2] * SIM_SCALE);
                    rp[mt * 2 + 1] += e; cp[nt * 2] += e;
                    if (i_hi == j_e) g_diag[i_hi] = e;
                }
                if (j_o < N) {
                    float e = exp2f(acc[mt][nt][3] * SIM_SCALE);
                    rp[mt * 2 + 1] += e; cp[nt * 2 + 1] += e;
                    if (i_hi == j_o) g_diag[i_hi] = e;
                }
            }
        }
    }

    #pragma unroll
    for (int r = 0; r < 8; r++) {
        float v = rp[r];
        v += __shfl_xor_sync(0xffffffffu, v, 1);
        v += __shfl_xor_sync(0xffffffffu, v, 2);
        if (tig == 0) {
            int mt = r >> 1, h = r & 1;
            atomicAdd(&sRow[warp_m * 64 + mt * 16 + h * 8 + g], v);
        }
    }
    #pragma unroll
    for (int c = 0; c < 8; c++) {
        float v = cp[c];
        v += __shfl_xor_sync(0xffffffffu, v, 4);
        v += __shfl_xor_sync(0xffffffffu, v, 8);
        v += __shfl_xor_sync(0xffffffffu, v, 16);
        if (g == 0) {
            int nt = c >> 1, par = c & 1;
            atomicAdd(&sCol[warp_n * 32 + nt * 8 + 2 * tig + par], v);
        }
    }
    __syncthreads();

    if (t < TILE) {
        int i = i0 + t;
        if (i < N) atomicAdd(&g_rowsum[i], sRow[t]);
        int j = j0 + t;
        if (j < N) atomicAdd(&g_colsum[j], sCol[t]);
    }
}

// ---------------- motif loss: warp per (product, sign, motif) ----------------
__global__ void motif_kernel(const int* __restrict__ motif,
                             const int* __restrict__ neg_uv,
                             const float* __restrict__ b1,
                             const float* __restrict__ W2,
                             const float* __restrict__ b2,
                             int N, int M) {
    __shared__ double sd[8];
    int gwarp = (blockIdx.x * blockDim.x + threadIdx.x) >> 5;
    int lane = threadIdx.x & 31;
    int wib = threadIdx.x >> 5;
    int total = 4 * 2 * M;
    double local = 0.0;

    if (gwarp < total) {
        int p = gwarp / (2 * M);
        int rem = gwarp % (2 * M);
        int s = rem / M;
        int m = rem % M;
        int u, v, w;
        if (s == 0) { u = motif[m];  v = motif[M + m];  w = motif[2 * M + m]; }
        else        { u = neg_uv[m]; v = neg_uv[M + m]; w = motif[2 * M + m]; }
        const float* base = g_H + (size_t)p * N * 192;
        float acc = 0.f;
        #pragma unroll
        for (int rep = 0; rep < 2; rep++) {
            int j = lane + rep * 32;
            float h = base[(size_t)u * 192 + j]
                    + base[(size_t)v * 192 + 64 + j]
                    + base[(size_t)w * 192 + 128 + j]
                    + b1[j];
            h = fmaxf(h, 0.f);
            acc += h * W2[j];
        }
        #pragma unroll
        for (int off = 16; off; off >>= 1) acc += __shfl_xor_sync(0xffffffffu, acc, off);
        if (lane == 0) {
            float logit = acc + b2[0];
            float z = s ? -logit : logit;
            float ls = fminf(z, 0.f) - log1pf(expf(-fabsf(z)));
            local = (double)ls;
        }
    }
    if (lane == 0) sd[wib] = local;
    __syncthreads();
    if (threadIdx.x == 0) {
        double sum = 0.0;
        #pragma unroll
        for (int i = 0; i < 8; i++) sum += sd[i];
        atomicAdd(&g_macc, sum);
    }
}

// ---------------- contrastive-loss partial sums (parallel, fp32 logs) --------
__global__ void cl_partial_kernel(int N) {
    __shared__ double sd[256];
    int t = threadIdx.x;
    int j = blockIdx.x * 256 + t;
    double dl = 0.0;
    if (j < N) {
        float pos = g_diag[j];
        float lp = logf(pos);
        dl = (double)(2.f * lp - logf(g_colsum[j] - pos) - logf(g_rowsum[j] - pos));
    }
    sd[t] = dl;
    __syncthreads();
    #pragma unroll
    for (int s = 128; s > 0; s >>= 1) {
        if (t < s) sd[t] += sd[t + s];
        __syncthreads();
    }
    if (t == 0) atomicAdd(&g_clacc, sd[0]);
}

// ---------------- combine -> scalar -------------------------------------------
__global__ void combine_kernel(float* __restrict__ out, int N, int M) {
    out[0] = (float)(-0.5 * g_clacc / (double)N - g_macc / (double)M);
}

// ---------------- launch ------------------------------------------------------
extern "C" void kernel_launch(void* const* d_in, const int* in_sizes, int n_in,
                              void* d_out, int out_size) {
    const float* x         = (const float*)d_in[0];
    const float* feats     = (const float*)d_in[1];
    const float* feat_free = (const float*)d_in[2];
    const float* ks        = (const float*)d_in[3];
    const float* Ws        = (const float*)d_in[4];
    const float* bias      = (const float*)d_in[5];
    const float* W_free    = (const float*)d_in[6];
    const float* b_free    = (const float*)d_in[7];
    const float* W1        = (const float*)d_in[8];
    const float* b1        = (const float*)d_in[9];
    const float* W2        = (const float*)d_in[10];
    const float* b2        = (const float*)d_in[11];
    const int*   motif     = (const int*)d_in[12];
    const int*   neg_uv    = (const int*)d_in[13];
    float* out = (float*)d_out;

    int N = in_sizes[0] / EMB;        // 10000
    int M = in_sizes[12] / 3;         // 50000

    cudaFuncSetAttribute(sim_hmma_kernel,
                         cudaFuncAttributeMaxDynamicSharedMemorySize, SIM_SMEM);

    // 1: normalize riemannian features
    {
        int rows = 3 * N;
        int blocks = (rows * 32 + 255) / 256;
        norm_feats_kernel<<<blocks, 256>>>(feats, ks, N);
    }
    // 2: normalize x (also zeros accumulators)
    norm_x_kernel<<<N, 256>>>(x, N);
    // 3: H = product @ W1 (needs g_prod only)
    {
        int total = 4 * N * 48;
        build_H_kernel<<<(total + 255) / 256, 256>>>(feat_free, W1, N);
    }
    // 4: build x2  (profiled slot)
    build_x2_kernel<<<(N + X2_ROWS - 1) / X2_ROWS, 256>>>(
        feat_free, ks, Ws, bias, W_free, b_free, N);
    // 5: fused sim GEMM + reductions
    {
        dim3 grid((N + TILE - 1) / TILE, (N + TILE - 1) / TILE);
        sim_hmma_kernel<<<grid, 256, SIM_SMEM>>>(N);
    }
    // 6: motif loss
    {
        int warps = 4 * 2 * M;
        int blocks = (warps * 32 + 255) / 256;
        motif_kernel<<<blocks, 256>>>(motif, neg_uv, b1, W2, b2, N, M);
    }
    // 7: contrastive partials, 8: combine
    cl_partial_kernel<<<(N + 255) / 256, 256>>>(N);
    combine_kernel<<<1, 1>>>(out, N, M);
}

// round 8
// speedup vs baseline: 6.1549x; 1.1299x over previous
#include <cuda_runtime.h>
#include <cuda_bf16.h>
#include <math.h>
#include <stdint.h>

// Problem-instance maxima (N=10000, M=50000, fixed shapes per reference)
#define NMAX 10016
#define D_IN 32
#define DOUT 64
#define EMB 256
#define EPS 1e-5f
// log2(e)/TEMP,  TEMP = 0.2
#define SIM_SCALE 7.2134752044448170f

// ---------------- scratch (static device globals; no allocation) -------------
__device__ float g_prod[3 * NMAX * D_IN];             // normalized riemannian feats
__device__ __nv_bfloat16 g_xa[NMAX * EMB];            // row-normalized x   (bf16)
__device__ __nv_bfloat16 g_xb[NMAX * EMB];            // row-normalized x2  (bf16)
__device__ float g_H[4 * NMAX * 192];                 // MLP layer-1 partials
__device__ float g_rowsum[NMAX];
__device__ float g_colsum[NMAX];
__device__ float g_diag[NMAX];
__device__ double g_macc;                             // motif log-sigmoid sum
__device__ double g_clacc;                            // contrastive log-ratio sum

__device__ __forceinline__ uint32_t smem_u32(const void* p) {
    uint32_t a;
    asm("{ .reg .u64 t; cvta.to.shared.u64 t, %1; cvt.u32.u64 %0, t; }" : "=r"(a) : "l"(p));
    return a;
}
__device__ __forceinline__ void cp_async16(uint32_t dst, const void* src, bool pred) {
    int sz = pred ? 16 : 0;
    asm volatile("cp.async.cg.shared.global [%0], [%1], 16, %2;"
                 :: "r"(dst), "l"(src), "r"(sz) : "memory");
}
#define CP_COMMIT() asm volatile("cp.async.commit_group;" ::: "memory")
#define CP_WAIT(n)  asm volatile("cp.async.wait_group %0;" :: "n"(n) : "memory")

__device__ __forceinline__ uint32_t pack_bf16x2(float a, float b) {
    __nv_bfloat162 h = __floats2bfloat162_rn(a, b);
    return *reinterpret_cast<uint32_t*>(&h);
}

// ---------------- 1: normalize feats -> products ------------------------------
__global__ void norm_feats_kernel(const float* __restrict__ feats,
                                  const float* __restrict__ ks, int N) {
    int row = (blockIdx.x * blockDim.x + threadIdx.x) >> 5;
    int lane = threadIdx.x & 31;
    if (row >= 3 * N) return;
    float v = feats[row * D_IN + lane];
    float sq = v * v;
    #pragma unroll
    for (int off = 16; off; off >>= 1) sq += __shfl_xor_sync(0xffffffffu, sq, off);
    int f = row / N;
    float k = ks[f];
    float scale = 0.45f / (sqrtf(sq) * sqrtf(fabsf(k)));
    g_prod[row * D_IN + lane] = v * scale;
}

// ---------------- 2: normalize x rows -> bf16, warp/row (+ zero accum) --------
__global__ void norm_x_kernel(const float* __restrict__ x, int N) {
    int tid = blockIdx.x * blockDim.x + threadIdx.x;
    if (tid < N) { g_rowsum[tid] = 0.f; g_colsum[tid] = 0.f; }
    if (tid == 0) { g_macc = 0.0; g_clacc = 0.0; }
    int row = tid >> 5;
    int lane = tid & 31;
    if (row >= N) return;
    const float4* rp = (const float4*)(x + (size_t)row * EMB);
    float4 v0 = rp[lane * 2];
    float4 v1 = rp[lane * 2 + 1];
    float sq = v0.x * v0.x + v0.y * v0.y + v0.z * v0.z + v0.w * v0.w
             + v1.x * v1.x + v1.y * v1.y + v1.z * v1.z + v1.w * v1.w;
    #pragma unroll
    for (int off = 16; off; off >>= 1) sq += __shfl_xor_sync(0xffffffffu, sq, off);
    float inv = rsqrtf(sq);
    uint4 o;
    o.x = pack_bf16x2(v0.x * inv, v0.y * inv);
    o.y = pack_bf16x2(v0.z * inv, v0.w * inv);
    o.z = pack_bf16x2(v1.x * inv, v1.y * inv);
    o.w = pack_bf16x2(v1.z * inv, v1.w * inv);
    *(uint4*)(g_xa + (size_t)row * EMB + lane * 8) = o;
}

// ---------------- 3: build x2 (random mapping), normalize, -> bf16 ------------
#define X2_ROWS 8
__global__ __launch_bounds__(256) void build_x2_kernel(
        const float* __restrict__ feat_free,
        const float* __restrict__ ks,
        const float* __restrict__ Ws,
        const float* __restrict__ bias,
        const float* __restrict__ W_free,
        const float* __restrict__ b_free,
        int N) {
    __shared__ float ws[3 * 32 * 65];     // [f][c][col], c-stride 65
    __shared__ float wf[32 * 65];         // [c][col]
    __shared__ float xi[X2_ROWS][128];
    __shared__ float red[X2_ROWS][256];
    const int n0 = blockIdx.x * X2_ROWS;
    const int t = threadIdx.x;

    #pragma unroll
    for (int k = 0; k < 6; k++) {
        int idx4 = t + k * 256;
        float4 v = ((const float4*)Ws)[idx4];
        int row = idx4 >> 3;
        int c0 = (idx4 & 7) * 4;
        int f = row >> 6, col = row & 63;
        float* dst = ws + f * (32 * 65) + col;
        dst[(c0 + 0) * 65] = v.x; dst[(c0 + 1) * 65] = v.y;
        dst[(c0 + 2) * 65] = v.z; dst[(c0 + 3) * 65] = v.w;
    }
    #pragma unroll
    for (int k = 0; k < 2; k++) {
        int idx4 = t + k * 256;
        float4 v = ((const float4*)W_free)[idx4];
        int col = idx4 >> 3;
        int c0 = (idx4 & 7) * 4;
        float* dst = wf + col;
        dst[(c0 + 0) * 65] = v.x; dst[(c0 + 1) * 65] = v.y;
        dst[(c0 + 2) * 65] = v.z; dst[(c0 + 3) * 65] = v.w;
    }
    #pragma unroll
    for (int rr = 0; rr < 4; rr++) {
        int idx = t + rr * 256;
        int r = idx >> 7;
        int c = idx & 127;
        int n = n0 + r;
        float v;
        if (n < N) {
            v = (c < 96) ? g_prod[((c >> 5) * N + n) * D_IN + (c & 31)]
                         : feat_free[n * D_IN + (c - 96)];
        } else v = 1.f;
        xi[r][c] = v;
    }
    __syncthreads();

    const int f = t >> 6;
    const int col = t & 63;
    const float kf = (f < 3) ? ks[f] : 0.f;
    const float bv = (f < 3) ? bias[f * DOUT + col] : b_free[col];

    float z[X2_ROWS];
    #pragma unroll
    for (int r = 0; r < X2_ROWS; r++) {
        float zv;
        if (f < 3) {
            const float* xv = xi[r] + f * D_IN;
            const float* wv = ws + f * (32 * 65) + col;
            float nsq = 0.f, dot = 0.f;
            #pragma unroll
            for (int c = 0; c < D_IN; c++) {
                float xc = xv[c];
                nsq += xc * xc;
                dot += xc * wv[c * 65];
            }
            float div = nsq - 2.f * dot + 1.f;
            float num = 1.f + kf * nsq;
            float dist = logf(num / (div + EPS));
            zv = expf(15.5f * dist) * cosf(dist + bv);
        } else {
            const float* xv = xi[r] + 3 * D_IN;
            const float* wv = wf + col;
            float dot = 0.f;
            #pragma unroll
            for (int c = 0; c < D_IN; c++) dot += xv[c] * wv[c * 65];
            zv = expf(15.5f * dot) * cosf(dot + bv);
        }
        z[r] = zv;
        red[r][t] = zv * zv;
    }
    __syncthreads();
    #pragma unroll
    for (int s = 128; s > 0; s >>= 1) {
        if (t < s) {
            #pragma unroll
            for (int r = 0; r < X2_ROWS; r++) red[r][t] += red[r][t + s];
        }
        __syncthreads();
    }
    #pragma unroll
    for (int r = 0; r < X2_ROWS; r++) {
        int n = n0 + r;
        if (n < N) {
            float inv = rsqrtf(red[r][0]);
            g_xb[n * EMB + t] = __float2bfloat16(z[r] * inv);
        }
    }
}

// ---------------- 4: H = product_p @ W1, W1 + rows cached in smem -------------
#define BH_PAIRS 16
__global__ __launch_bounds__(256) void build_H_kernel(
        const float* __restrict__ feat_free,
        const float* __restrict__ W1, int N) {
    __shared__ float w1s[96 * 64];        // 24 KB
    __shared__ float rows[BH_PAIRS][32];
    const int t = threadIdx.x;
    const int q0 = blockIdx.x * BH_PAIRS;

    #pragma unroll
    for (int k = 0; k < 6; k++) {
        int i4 = t + k * 256;
        ((float4*)w1s)[i4] = ((const float4*)W1)[i4];
    }
    #pragma unroll
    for (int k = 0; k < 2; k++) {
        int idx = t + k * 256;
        int pr = idx >> 5, c = idx & 31;
        int q = q0 + pr;
        float v = 0.f;
        if (q < 4 * N) {
            int p = q / N, n = q % N;
            v = (p < 3) ? g_prod[((size_t)p * N + n) * D_IN + c]
                        : feat_free[(size_t)n * D_IN + c];
        }
        rows[pr][c] = v;
    }
    __syncthreads();

    const int pr = t >> 4;
    const int jj = (t & 15) * 4;
    const int q = q0 + pr;
    if (q < 4 * N) {
        #pragma unroll
        for (int part = 0; part < 3; part++) {
            float4 s = make_float4(0.f, 0.f, 0.f, 0.f);
            #pragma unroll
            for (int c = 0; c < 32; c++) {
                float r = rows[pr][c];
                float4 w = *(const float4*)&w1s[(part * 32 + c) * 64 + jj];
                s.x += r * w.x; s.y += r * w.y; s.z += r * w.z; s.w += r * w.w;
            }
            *(float4*)(g_H + (size_t)q * 192 + part * 64 + jj) = s;
        }
    }
}

// ---------------- 5: sim GEMM: bf16 mma.sync, 1 barrier per k-iter -------------
#define TILE 128
#define BK 64
#define RS 72                 // smem row stride in bf16 elems (144B, conflict-free)
#define MAT_BYTES (TILE * RS * 2)          // 18432
#define STAGE_BYTES (2 * MAT_BYTES)        // 36864
#define SIM_SMEM (2 * STAGE_BYTES)         // 73728

__global__ __launch_bounds__(256, 2) void sim_hmma_kernel(int N) {
    extern __shared__ char dynsm[];
    __shared__ float sRow[TILE];
    __shared__ float sCol[TILE];

    const uint32_t sbase = smem_u32(dynsm);
    const int t = threadIdx.x;
    const int lane = t & 31;
    const int wid = t >> 5;
    const int warp_m = wid & 1;
    const int warp_n = wid >> 1;
    const int g = lane >> 2;
    const int tig = lane & 3;
    const int i0 = blockIdx.y * TILE;
    const int j0 = blockIdx.x * TILE;

    const __nv_bfloat16* GA = g_xa;
    const __nv_bfloat16* GB = g_xb;

    if (t < TILE) { sRow[t] = 0.f; sCol[t] = 0.f; }

    // ---- prologue: stage 0
    {
        #pragma unroll
        for (int it = 0; it < 4; it++) {
            int id = t + it * 256;
            int row = id >> 3, ch = id & 7;
            cp_async16(sbase + row * 144 + ch * 16,
                       GA + (size_t)(i0 + row) * EMB + ch * 8, i0 + row < N);
        }
        #pragma unroll
        for (int it = 0; it < 4; it++) {
            int id = t + it * 256;
            int row = id >> 3, ch = id & 7;
            cp_async16(sbase + MAT_BYTES + row * 144 + ch * 16,
                       GB + (size_t)(j0 + row) * EMB + ch * 8, j0 + row < N);
        }
        CP_COMMIT();
    }

    float acc[4][4][4];
    #pragma unroll
    for (int mt = 0; mt < 4; mt++)
        #pragma unroll
        for (int nt = 0; nt < 4; nt++)
            #pragma unroll
            for (int c = 0; c < 4; c++) acc[mt][nt][c] = 0.f;

    const int aRow = lane & 15;
    const int aCol = (lane >> 4) * 8;
    const int bRow = (lane & 7) + ((lane >> 4) << 3);
    const int bCol = ((lane >> 3) & 1) * 8;

    #pragma unroll
    for (int s = 0; s < EMB / BK; s++) {
        CP_WAIT(0);
        __syncthreads();

        // prefetch next stage (safe: all warps finished reading this buffer
        // in iteration s-1, enforced by the barrier above)
        if (s + 1 < EMB / BK) {
            uint32_t dst = sbase + ((s + 1) & 1) * STAGE_BYTES;
            const int koff = (s + 1) * BK;
            #pragma unroll
            for (int it = 0; it < 4; it++) {
                int id = t + it * 256;
                int row = id >> 3, ch = id & 7;
                cp_async16(dst + row * 144 + ch * 16,
                           GA + (size_t)(i0 + row) * EMB + koff + ch * 8, i0 + row < N);
            }
            #pragma unroll
            for (int it = 0; it < 4; it++) {
                int id = t + it * 256;
                int row = id >> 3, ch = id & 7;
                cp_async16(dst + MAT_BYTES + row * 144 + ch * 16,
                           GB + (size_t)(j0 + row) * EMB + koff + ch * 8, j0 + row < N);
            }
            CP_COMMIT();
        }

        const uint32_t aB = sbase + (s & 1) * STAGE_BYTES;
        const uint32_t bB = aB + MAT_BYTES;

        #pragma unroll
        for (int kk = 0; kk < BK / 16; kk++) {
            const int k0 = kk * 16;
            uint32_t a[4][4];
            #pragma unroll
            for (int mt = 0; mt < 4; mt++) {
                uint32_t addr = aB + ((warp_m * 64 + mt * 16 + aRow) * RS + k0 + aCol) * 2;
                asm volatile("ldmatrix.sync.aligned.m8n8.x4.shared.b16 {%0,%1,%2,%3}, [%4];"
                             : "=r"(a[mt][0]), "=r"(a[mt][1]), "=r"(a[mt][2]), "=r"(a[mt][3])
                             : "r"(addr));
            }
            uint32_t b[4][2];
            #pragma unroll
            for (int bq = 0; bq < 2; bq++) {
                uint32_t addr = bB + ((warp_n * 32 + bq * 16 + bRow) * RS + k0 + bCol) * 2;
                uint32_t r0, r1, r2, r3;
                asm volatile("ldmatrix.sync.aligned.m8n8.x4.shared.b16 {%0,%1,%2,%3}, [%4];"
                             : "=r"(r0), "=r"(r1), "=r"(r2), "=r"(r3)
                             : "r"(addr));
                b[bq * 2][0] = r0;     b[bq * 2][1] = r1;
                b[bq * 2 + 1][0] = r2; b[bq * 2 + 1][1] = r3;
            }
            #pragma unroll
            for (int mt = 0; mt < 4; mt++)
                #pragma unroll
                for (int nt = 0; nt < 4; nt++) {
                    asm volatile(
                        "mma.sync.aligned.m16n8k16.row.col.f32.bf16.bf16.f32 "
                        "{%0,%1,%2,%3}, {%4,%5,%6,%7}, {%8,%9}, {%0,%1,%2,%3};"
                        : "+f"(acc[mt][nt][0]), "+f"(acc[mt][nt][1]),
                          "+f"(acc[mt][nt][2]), "+f"(acc[mt][nt][3])
                        : "r"(a[mt][0]), "r"(a[mt][1]), "r"(a[mt][2]), "r"(a[mt][3]),
                          "r"(b[nt][0]), "r"(b[nt][1]));
                }
        }
    }

    // ---- epilogue: exp2 + row/col/diag reductions -----------------------------
    float rp[8];
    float cp[8];
    #pragma unroll
    for (int r = 0; r < 8; r++) { rp[r] = 0.f; cp[r] = 0.f; }

    #pragma unroll
    for (int mt = 0; mt < 4; mt++) {
        int i_lo = i0 + warp_m * 64 + mt * 16 + g;
        int i_hi = i_lo + 8;
        #pragma unroll
        for (int nt = 0; nt < 4; nt++) {
            int j_e = j0 + warp_n * 32 + nt * 8 + 2 * tig;
            int j_o = j_e + 1;
            if (i_lo < N) {
                if (j_e < N) {
                    float e = exp2f(acc[mt][nt][0] * SIM_SCALE);
                    rp[mt * 2] += e; cp[nt * 2] += e;
                    if (i_lo == j_e) g_diag[i_lo] = e;
                }
                if (j_o < N) {
                    float e = exp2f(acc[mt][nt][1] * SIM_SCALE);
                    rp[mt * 2] += e; cp[nt * 2 + 1] += e;
                    if (i_lo == j_o) g_diag[i_lo] = e;
                }
            }
            if (i_hi < N) {
                if (j_e < N) {
                    float e = exp2f(acc[mt][nt][2] * SIM_SCALE);
                    rp[mt * 2 + 1] += e; cp[nt * 2] += e;
                    if (i_hi == j_e) g_diag[i_hi] = e;
                }
                if (j_o < N) {
                    float e = exp2f(acc[mt][nt][3] * SIM_SCALE);
                    rp[mt * 2 + 1] += e; cp[nt * 2 + 1] += e;
                    if (i_hi == j_o) g_diag[i_hi] = e;
                }
            }
        }
    }

    #pragma unroll
    for (int r = 0; r < 8; r++) {
        float v = rp[r];
        v += __shfl_xor_sync(0xffffffffu, v, 1);
        v += __shfl_xor_sync(0xffffffffu, v, 2);
        if (tig == 0) {
            int mt = r >> 1, h = r & 1;
            atomicAdd(&sRow[warp_m * 64 + mt * 16 + h * 8 + g], v);
        }
    }
    #pragma unroll
    for (int c = 0; c < 8; c++) {
        float v = cp[c];
        v += __shfl_xor_sync(0xffffffffu, v, 4);
        v += __shfl_xor_sync(0xffffffffu, v, 8);
        v += __shfl_xor_sync(0xffffffffu, v, 16);
        if (g == 0) {
            int nt = c >> 1, par = c & 1;
            atomicAdd(&sCol[warp_n * 32 + nt * 8 + 2 * tig + par], v);
        }
    }
    __syncthreads();

    if (t < TILE) {
        int i = i0 + t;
        if (i < N) atomicAdd(&g_rowsum[i], sRow[t]);
        int j = j0 + t;
        if (j < N) atomicAdd(&g_colsum[j], sCol[t]);
    }
}

// ---------------- 6: motif loss: warp per motif, loop (p, sign) ---------------
__global__ void motif_kernel(const int* __restrict__ motif,
                             const int* __restrict__ neg_uv,
                             const float* __restrict__ b1,
                             const float* __restrict__ W2,
                             const float* __restrict__ b2,
                             int N, int M) {
    __shared__ double sd[8];
    int gw = (blockIdx.x * blockDim.x + threadIdx.x) >> 5;
    int lane = threadIdx.x & 31;
    int wib = threadIdx.x >> 5;
    double local = 0.0;

    if (gw < M) {
        int m = gw;
        int u0 = motif[m], v0 = motif[M + m], w0 = motif[2 * M + m];
        int u1 = neg_uv[m], v1 = neg_uv[M + m];
        int j1 = lane + 32;
        float b1a = b1[lane], b1b = b1[j1];
        float w2a = W2[lane], w2b = W2[j1];
        float bb2 = b2[0];

        #pragma unroll
        for (int p = 0; p < 4; p++) {
            const float* base = g_H + (size_t)p * N * 192;
            #pragma unroll
            for (int s = 0; s < 2; s++) {
                int u = s ? u1 : u0;
                int v = s ? v1 : v0;
                float h0 = base[(size_t)u * 192 + lane]
                         + base[(size_t)v * 192 + 64 + lane]
                         + base[(size_t)w0 * 192 + 128 + lane] + b1a;
                float h1 = base[(size_t)u * 192 + j1]
                         + base[(size_t)v * 192 + 64 + j1]
                         + base[(size_t)w0 * 192 + 128 + j1] + b1b;
                float acc = fmaxf(h0, 0.f) * w2a + fmaxf(h1, 0.f) * w2b;
                #pragma unroll
                for (int off = 16; off; off >>= 1)
                    acc += __shfl_xor_sync(0xffffffffu, acc, off);
                if (lane == 0) {
                    float logit = acc + bb2;
                    float z = s ? -logit : logit;
                    local += (double)(fminf(z, 0.f) - log1pf(expf(-fabsf(z))));
                }
            }
        }
    }
    if (lane == 0) sd[wib] = local;
    __syncthreads();
    if (threadIdx.x == 0) {
        double sum = 0.0;
        #pragma unroll
        for (int i = 0; i < 8; i++) sum += sd[i];
        atomicAdd(&g_macc, sum);
    }
}

// ---------------- 7: contrastive-loss partial sums ----------------------------
__global__ void cl_partial_kernel(int N) {
    __shared__ double sd[256];
    int t = threadIdx.x;
    int j = blockIdx.x * 256 + t;
    double dl = 0.0;
    if (j < N) {
        float pos = g_diag[j];
        float lp = logf(pos);
        dl = (double)(2.f * lp - logf(g_colsum[j] - pos) - logf(g_rowsum[j] - pos));
    }
    sd[t] = dl;
    __syncthreads();
    #pragma unroll
    for (int s = 128; s > 0; s >>= 1) {
        if (t < s) sd[t] += sd[t + s];
        __syncthreads();
    }
    if (t == 0) atomicAdd(&g_clacc, sd[0]);
}

// ---------------- 8: combine -> scalar -----------------------------------------
__global__ void combine_kernel(float* __restrict__ out, int N, int M) {
    out[0] = (float)(-0.5 * g_clacc / (double)N - g_macc / (double)M);
}

// ---------------- launch --------------------------------------------------------
extern "C" void kernel_launch(void* const* d_in, const int* in_sizes, int n_in,
                              void* d_out, int out_size) {
    const float* x         = (const float*)d_in[0];
    const float* feats     = (const float*)d_in[1];
    const float* feat_free = (const float*)d_in[2];
    const float* ks        = (const float*)d_in[3];
    const float* Ws        = (const float*)d_in[4];
    const float* bias      = (const float*)d_in[5];
    const float* W_free    = (const float*)d_in[6];
    const float* b_free    = (const float*)d_in[7];
    const float* W1        = (const float*)d_in[8];
    const float* b1        = (const float*)d_in[9];
    const float* W2        = (const float*)d_in[10];
    const float* b2        = (const float*)d_in[11];
    const int*   motif     = (const int*)d_in[12];
    const int*   neg_uv    = (const int*)d_in[13];
    float* out = (float*)d_out;

    int N = in_sizes[0] / EMB;        // 10000
    int M = in_sizes[12] / 3;         // 50000

    cudaFuncSetAttribute(sim_hmma_kernel,
                         cudaFuncAttributeMaxDynamicSharedMemorySize, SIM_SMEM);

    // 1: normalize riemannian features
    {
        int rows = 3 * N;
        norm_feats_kernel<<<(rows * 32 + 255) / 256, 256>>>(feats, ks, N);
    }
    // 2: normalize x (warp per row; also zeros accumulators)
    norm_x_kernel<<<(N * 32 + 255) / 256, 256>>>(x, N);
    // 3: build x2
    build_x2_kernel<<<(N + X2_ROWS - 1) / X2_ROWS, 256>>>(
        feat_free, ks, Ws, bias, W_free, b_free, N);
    // 4: H = product @ W1  (profiled slot)
    build_H_kernel<<<(4 * N + BH_PAIRS - 1) / BH_PAIRS, 256>>>(feat_free, W1, N);
    // 5: fused sim GEMM + reductions
    {
        dim3 grid((N + TILE - 1) / TILE, (N + TILE - 1) / TILE);
        sim_hmma_kernel<<<grid, 256, SIM_SMEM>>>(N);
    }
    // 6: motif loss (warp per motif)
    motif_kernel<<<(M * 32 + 255) / 256, 256>>>(motif, neg_uv, b1, W2, b2, N, M);
    // 7: contrastive partials, 8: combine
    cl_partial_kernel<<<(N + 255) / 256, 256>>>(N);
    combine_kernel<<<1, 1>>>(out, N, M);
}

// round 9
// speedup vs baseline: 6.8060x; 1.1058x over previous
#include <cuda_runtime.h>
#include <cuda_bf16.h>
#include <math.h>
#include <stdint.h>

// Problem-instance maxima (N=10000, M=50000, fixed shapes per reference)
#define NMAX 10016
#define D_IN 32
#define DOUT 64
#define EMB 256
#define EPS 1e-5f
// log2(e)/TEMP,  TEMP = 0.2
#define SIM_SCALE 7.2134752044448170f

// ---------------- scratch (static device globals; no allocation) -------------
__device__ float g_prod[3 * NMAX * D_IN];             // normalized riemannian feats
__device__ __nv_bfloat16 g_xa[NMAX * EMB];            // row-normalized x   (bf16)
__device__ __nv_bfloat16 g_xb[NMAX * EMB];            // row-normalized x2  (bf16)
__device__ float g_H[4 * NMAX * 192];                 // MLP layer-1 partials
__device__ float g_rowsum[NMAX];
__device__ float g_colsum[NMAX];
__device__ float g_diag[NMAX];
__device__ double g_macc;                             // motif log-sigmoid sum
__device__ double g_clacc;                            // contrastive log-ratio sum

__device__ __forceinline__ uint32_t smem_u32(const void* p) {
    uint32_t a;
    asm("{ .reg .u64 t; cvta.to.shared.u64 t, %1; cvt.u32.u64 %0, t; }" : "=r"(a) : "l"(p));
    return a;
}
__device__ __forceinline__ void cp_async16(uint32_t dst, const void* src, bool pred) {
    int sz = pred ? 16 : 0;
    asm volatile("cp.async.cg.shared.global [%0], [%1], 16, %2;"
                 :: "r"(dst), "l"(src), "r"(sz) : "memory");
}
#define CP_COMMIT() asm volatile("cp.async.commit_group;" ::: "memory")
#define CP_WAIT(n)  asm volatile("cp.async.wait_group %0;" :: "n"(n) : "memory")

__device__ __forceinline__ uint32_t pack_bf16x2(float a, float b) {
    __nv_bfloat162 h = __floats2bfloat162_rn(a, b);
    return *reinterpret_cast<uint32_t*>(&h);
}

// ---------------- 1: normalize feats -> products ------------------------------
__global__ void norm_feats_kernel(const float* __restrict__ feats,
                                  const float* __restrict__ ks, int N) {
    int row = (blockIdx.x * blockDim.x + threadIdx.x) >> 5;
    int lane = threadIdx.x & 31;
    if (row >= 3 * N) return;
    float v = feats[row * D_IN + lane];
    float sq = v * v;
    #pragma unroll
    for (int off = 16; off; off >>= 1) sq += __shfl_xor_sync(0xffffffffu, sq, off);
    int f = row / N;
    float k = ks[f];
    float scale = 0.45f / (sqrtf(sq) * sqrtf(fabsf(k)));
    g_prod[row * D_IN + lane] = v * scale;
}

// ---------------- 2: normalize x rows -> bf16, warp/row (+ zero accum) --------
__global__ void norm_x_kernel(const float* __restrict__ x, int N) {
    int tid = blockIdx.x * blockDim.x + threadIdx.x;
    if (tid < N) { g_rowsum[tid] = 0.f; g_colsum[tid] = 0.f; }
    if (tid == 0) { g_macc = 0.0; g_clacc = 0.0; }
    int row = tid >> 5;
    int lane = tid & 31;
    if (row >= N) return;
    const float4* rp = (const float4*)(x + (size_t)row * EMB);
    float4 v0 = rp[lane * 2];
    float4 v1 = rp[lane * 2 + 1];
    float sq = v0.x * v0.x + v0.y * v0.y + v0.z * v0.z + v0.w * v0.w
             + v1.x * v1.x + v1.y * v1.y + v1.z * v1.z + v1.w * v1.w;
    #pragma unroll
    for (int off = 16; off; off >>= 1) sq += __shfl_xor_sync(0xffffffffu, sq, off);
    float inv = rsqrtf(sq);
    uint4 o;
    o.x = pack_bf16x2(v0.x * inv, v0.y * inv);
    o.y = pack_bf16x2(v0.z * inv, v0.w * inv);
    o.z = pack_bf16x2(v1.x * inv, v1.y * inv);
    o.w = pack_bf16x2(v1.z * inv, v1.w * inv);
    *(uint4*)(g_xa + (size_t)row * EMB + lane * 8) = o;
}

// ---------------- 3: build x2 (random mapping), normalize, -> bf16 ------------
#define X2_ROWS 8
__global__ __launch_bounds__(256) void build_x2_kernel(
        const float* __restrict__ feat_free,
        const float* __restrict__ ks,
        const float* __restrict__ Ws,
        const float* __restrict__ bias,
        const float* __restrict__ W_free,
        const float* __restrict__ b_free,
        int N) {
    __shared__ float ws[3 * 32 * 65];     // [f][c][col], c-stride 65
    __shared__ float wf[32 * 65];         // [c][col]
    __shared__ float xi[X2_ROWS][128];
    __shared__ float red[X2_ROWS][256];
    const int n0 = blockIdx.x * X2_ROWS;
    const int t = threadIdx.x;

    #pragma unroll
    for (int k = 0; k < 6; k++) {
        int idx4 = t + k * 256;
        float4 v = ((const float4*)Ws)[idx4];
        int row = idx4 >> 3;
        int c0 = (idx4 & 7) * 4;
        int f = row >> 6, col = row & 63;
        float* dst = ws + f * (32 * 65) + col;
        dst[(c0 + 0) * 65] = v.x; dst[(c0 + 1) * 65] = v.y;
        dst[(c0 + 2) * 65] = v.z; dst[(c0 + 3) * 65] = v.w;
    }
    #pragma unroll
    for (int k = 0; k < 2; k++) {
        int idx4 = t + k * 256;
        float4 v = ((const float4*)W_free)[idx4];
        int col = idx4 >> 3;
        int c0 = (idx4 & 7) * 4;
        float* dst = wf + col;
        dst[(c0 + 0) * 65] = v.x; dst[(c0 + 1) * 65] = v.y;
        dst[(c0 + 2) * 65] = v.z; dst[(c0 + 3) * 65] = v.w;
    }
    #pragma unroll
    for (int rr = 0; rr < 4; rr++) {
        int idx = t + rr * 256;
        int r = idx >> 7;
        int c = idx & 127;
        int n = n0 + r;
        float v;
        if (n < N) {
            v = (c < 96) ? g_prod[((c >> 5) * N + n) * D_IN + (c & 31)]
                         : feat_free[n * D_IN + (c - 96)];
        } else v = 1.f;
        xi[r][c] = v;
    }
    __syncthreads();

    const int f = t >> 6;
    const int col = t & 63;
    const float kf = (f < 3) ? ks[f] : 0.f;
    const float bv = (f < 3) ? bias[f * DOUT + col] : b_free[col];

    float z[X2_ROWS];
    #pragma unroll
    for (int r = 0; r < X2_ROWS; r++) {
        float zv;
        if (f < 3) {
            const float* xv = xi[r] + f * D_IN;
            const float* wv = ws + f * (32 * 65) + col;
            float nsq = 0.f, dot = 0.f;
            #pragma unroll
            for (int c = 0; c < D_IN; c++) {
                float xc = xv[c];
                nsq += xc * xc;
                dot += xc * wv[c * 65];
            }
            float div = nsq - 2.f * dot + 1.f;
            float num = 1.f + kf * nsq;
            float dist = logf(num / (div + EPS));
            zv = expf(15.5f * dist) * cosf(dist + bv);
        } else {
            const float* xv = xi[r] + 3 * D_IN;
            const float* wv = wf + col;
            float dot = 0.f;
            #pragma unroll
            for (int c = 0; c < D_IN; c++) dot += xv[c] * wv[c * 65];
            zv = expf(15.5f * dot) * cosf(dot + bv);
        }
        z[r] = zv;
        red[r][t] = zv * zv;
    }
    __syncthreads();
    #pragma unroll
    for (int s = 128; s > 0; s >>= 1) {
        if (t < s) {
            #pragma unroll
            for (int r = 0; r < X2_ROWS; r++) red[r][t] += red[r][t + s];
        }
        __syncthreads();
    }
    #pragma unroll
    for (int r = 0; r < X2_ROWS; r++) {
        int n = n0 + r;
        if (n < N) {
            float inv = rsqrtf(red[r][0]);
            g_xb[n * EMB + t] = __float2bfloat16(z[r] * inv);
        }
    }
}

// ---------------- 4: sim GEMM: bf16 mma.sync (profiled slot) -------------------
#define TILE 128
#define BK 64
#define RS 72                 // smem row stride in bf16 elems (144B, conflict-free)
#define MAT_BYTES (TILE * RS * 2)          // 18432
#define STAGE_BYTES (2 * MAT_BYTES)        // 36864
#define SIM_SMEM (2 * STAGE_BYTES)         // 73728

__global__ __launch_bounds__(256, 2) void sim_hmma_kernel(int N) {
    extern __shared__ char dynsm[];
    __shared__ float sRow[TILE];
    __shared__ float sCol[TILE];

    const uint32_t sbase = smem_u32(dynsm);
    const int t = threadIdx.x;
    const int lane = t & 31;
    const int wid = t >> 5;
    const int warp_m = wid & 1;
    const int warp_n = wid >> 1;
    const int g = lane >> 2;
    const int tig = lane & 3;
    const int i0 = blockIdx.y * TILE;
    const int j0 = blockIdx.x * TILE;

    const __nv_bfloat16* GA = g_xa;
    const __nv_bfloat16* GB = g_xb;

    if (t < TILE) { sRow[t] = 0.f; sCol[t] = 0.f; }

    // ---- prologue: stage 0
    {
        #pragma unroll
        for (int it = 0; it < 4; it++) {
            int id = t + it * 256;
            int row = id >> 3, ch = id & 7;
            cp_async16(sbase + row * 144 + ch * 16,
                       GA + (size_t)(i0 + row) * EMB + ch * 8, i0 + row < N);
        }
        #pragma unroll
        for (int it = 0; it < 4; it++) {
            int id = t + it * 256;
            int row = id >> 3, ch = id & 7;
            cp_async16(sbase + MAT_BYTES + row * 144 + ch * 16,
                       GB + (size_t)(j0 + row) * EMB + ch * 8, j0 + row < N);
        }
        CP_COMMIT();
    }

    float acc[4][4][4];
    #pragma unroll
    for (int mt = 0; mt < 4; mt++)
        #pragma unroll
        for (int nt = 0; nt < 4; nt++)
            #pragma unroll
            for (int c = 0; c < 4; c++) acc[mt][nt][c] = 0.f;

    const int aRow = lane & 15;
    const int aCol = (lane >> 4) * 8;
    const int bRow = (lane & 7) + ((lane >> 4) << 3);
    const int bCol = ((lane >> 3) & 1) * 8;

    #pragma unroll
    for (int s = 0; s < EMB / BK; s++) {
        CP_WAIT(0);
        __syncthreads();

        if (s + 1 < EMB / BK) {
            uint32_t dst = sbase + ((s + 1) & 1) * STAGE_BYTES;
            const int koff = (s + 1) * BK;
            #pragma unroll
            for (int it = 0; it < 4; it++) {
                int id = t + it * 256;
                int row = id >> 3, ch = id & 7;
                cp_async16(dst + row * 144 + ch * 16,
                           GA + (size_t)(i0 + row) * EMB + koff + ch * 8, i0 + row < N);
            }
            #pragma unroll
            for (int it = 0; it < 4; it++) {
                int id = t + it * 256;
                int row = id >> 3, ch = id & 7;
                cp_async16(dst + MAT_BYTES + row * 144 + ch * 16,
                           GB + (size_t)(j0 + row) * EMB + koff + ch * 8, j0 + row < N);
            }
            CP_COMMIT();
        }

        const uint32_t aB = sbase + (s & 1) * STAGE_BYTES;
        const uint32_t bB = aB + MAT_BYTES;

        #pragma unroll
        for (int kk = 0; kk < BK / 16; kk++) {
            const int k0 = kk * 16;
            uint32_t a[4][4];
            #pragma unroll
            for (int mt = 0; mt < 4; mt++) {
                uint32_t addr = aB + ((warp_m * 64 + mt * 16 + aRow) * RS + k0 + aCol) * 2;
                asm volatile("ldmatrix.sync.aligned.m8n8.x4.shared.b16 {%0,%1,%2,%3}, [%4];"
                             : "=r"(a[mt][0]), "=r"(a[mt][1]), "=r"(a[mt][2]), "=r"(a[mt][3])
                             : "r"(addr));
            }
            uint32_t b[4][2];
            #pragma unroll
            for (int bq = 0; bq < 2; bq++) {
                uint32_t addr = bB + ((warp_n * 32 + bq * 16 + bRow) * RS + k0 + bCol) * 2;
                uint32_t r0, r1, r2, r3;
                asm volatile("ldmatrix.sync.aligned.m8n8.x4.shared.b16 {%0,%1,%2,%3}, [%4];"
                             : "=r"(r0), "=r"(r1), "=r"(r2), "=r"(r3)
                             : "r"(addr));
                b[bq * 2][0] = r0;     b[bq * 2][1] = r1;
                b[bq * 2 + 1][0] = r2; b[bq * 2 + 1][1] = r3;
            }
            #pragma unroll
            for (int mt = 0; mt < 4; mt++)
                #pragma unroll
                for (int nt = 0; nt < 4; nt++) {
                    asm volatile(
                        "mma.sync.aligned.m16n8k16.row.col.f32.bf16.bf16.f32 "
                        "{%0,%1,%2,%3}, {%4,%5,%6,%7}, {%8,%9}, {%0,%1,%2,%3};"
                        : "+f"(acc[mt][nt][0]), "+f"(acc[mt][nt][1]),
                          "+f"(acc[mt][nt][2]), "+f"(acc[mt][nt][3])
                        : "r"(a[mt][0]), "r"(a[mt][1]), "r"(a[mt][2]), "r"(a[mt][3]),
                          "r"(b[nt][0]), "r"(b[nt][1]));
                }
        }
    }

    // ---- epilogue: exp2 + row/col/diag reductions -----------------------------
    const bool full = (i0 + TILE <= N) && (j0 + TILE <= N);
    const bool isdiag = (i0 == j0);

    float rp[8];
    float cp[8];
    #pragma unroll
    for (int r = 0; r < 8; r++) { rp[r] = 0.f; cp[r] = 0.f; }

    if (full) {
        // fast path: no bounds checks (6162 / 6241 tiles)
        #pragma unroll
        for (int mt = 0; mt < 4; mt++) {
            #pragma unroll
            for (int nt = 0; nt < 4; nt++) {
                float e0 = exp2f(acc[mt][nt][0] * SIM_SCALE);
                float e1 = exp2f(acc[mt][nt][1] * SIM_SCALE);
                float e2 = exp2f(acc[mt][nt][2] * SIM_SCALE);
                float e3 = exp2f(acc[mt][nt][3] * SIM_SCALE);
                rp[mt * 2]     += e0 + e1;
                rp[mt * 2 + 1] += e2 + e3;
                cp[nt * 2]     += e0 + e2;
                cp[nt * 2 + 1] += e1 + e3;
            }
        }
        if (isdiag) {
            #pragma unroll
            for (int mt = 0; mt < 4; mt++) {
                int i_lo = i0 + warp_m * 64 + mt * 16 + g;
                int i_hi = i_lo + 8;
                #pragma unroll
                for (int nt = 0; nt < 4; nt++) {
                    int j_e = j0 + warp_n * 32 + nt * 8 + 2 * tig;
                    int j_o = j_e + 1;
                    if (i_lo == j_e) g_diag[i_lo] = exp2f(acc[mt][nt][0] * SIM_SCALE);
                    if (i_lo == j_o) g_diag[i_lo] = exp2f(acc[mt][nt][1] * SIM_SCALE);
                    if (i_hi == j_e) g_diag[i_hi] = exp2f(acc[mt][nt][2] * SIM_SCALE);
                    if (i_hi == j_o) g_diag[i_hi] = exp2f(acc[mt][nt][3] * SIM_SCALE);
                }
            }
        }
    } else {
        // edge path: full bounds + diag checks
        #pragma unroll
        for (int mt = 0; mt < 4; mt++) {
            int i_lo = i0 + warp_m * 64 + mt * 16 + g;
            int i_hi = i_lo + 8;
            #pragma unroll
            for (int nt = 0; nt < 4; nt++) {
                int j_e = j0 + warp_n * 32 + nt * 8 + 2 * tig;
                int j_o = j_e + 1;
                if (i_lo < N) {
                    if (j_e < N) {
                        float e = exp2f(acc[mt][nt][0] * SIM_SCALE);
                        rp[mt * 2] += e; cp[nt * 2] += e;
                        if (i_lo == j_e) g_diag[i_lo] = e;
                    }
                    if (j_o < N) {
                        float e = exp2f(acc[mt][nt][1] * SIM_SCALE);
                        rp[mt * 2] += e; cp[nt * 2 + 1] += e;
                        if (i_lo == j_o) g_diag[i_lo] = e;
                    }
                }
                if (i_hi < N) {
                    if (j_e < N) {
                        float e = exp2f(acc[mt][nt][2] * SIM_SCALE);
                        rp[mt * 2 + 1] += e; cp[nt * 2] += e;
                        if (i_hi == j_e) g_diag[i_hi] = e;
                    }
                    if (j_o < N) {
                        float e = exp2f(acc[mt][nt][3] * SIM_SCALE);
                        rp[mt * 2 + 1] += e; cp[nt * 2 + 1] += e;
                        if (i_hi == j_o) g_diag[i_hi] = e;
                    }
                }
            }
        }
    }

    #pragma unroll
    for (int r = 0; r < 8; r++) {
        float v = rp[r];
        v += __shfl_xor_sync(0xffffffffu, v, 1);
        v += __shfl_xor_sync(0xffffffffu, v, 2);
        if (tig == 0) {
            int mt = r >> 1, h = r & 1;
            atomicAdd(&sRow[warp_m * 64 + mt * 16 + h * 8 + g], v);
        }
    }
    #pragma unroll
    for (int c = 0; c < 8; c++) {
        float v = cp[c];
        v += __shfl_xor_sync(0xffffffffu, v, 4);
        v += __shfl_xor_sync(0xffffffffu, v, 8);
        v += __shfl_xor_sync(0xffffffffu, v, 16);
        if (g == 0) {
            int nt = c >> 1, par = c & 1;
            atomicAdd(&sCol[warp_n * 32 + nt * 8 + 2 * tig + par], v);
        }
    }
    __syncthreads();

    if (t < TILE) {
        int i = i0 + t;
        if (i < N) atomicAdd(&g_rowsum[i], sRow[t]);
        int j = j0 + t;
        if (j < N) atomicAdd(&g_colsum[j], sCol[t]);
    }
}

// ---------------- 5: H = product_p @ W1 (4 rows x 4 cols per thread) ----------
#define BH_ROWS 64
__global__ __launch_bounds__(256) void build_H_kernel(
        const float* __restrict__ feat_free,
        const float* __restrict__ W1, int N) {
    __shared__ float w1s[96 * 64];        // 24 KB
    __shared__ float rows[BH_ROWS][33];   // 8.25 KB, padded
    const int t = threadIdx.x;
    const int q0 = blockIdx.x * BH_ROWS;

    #pragma unroll
    for (int k = 0; k < 6; k++) {
        int i4 = t + k * 256;
        ((float4*)w1s)[i4] = ((const float4*)W1)[i4];
    }
    #pragma unroll
    for (int k = 0; k < 8; k++) {
        int idx = t + k * 256;
        int r = idx >> 5, c = idx & 31;
        int q = q0 + r;
        float v = 0.f;
        if (q < 4 * N) {
            int p = q / N, n = q % N;
            v = (p < 3) ? g_prod[((size_t)p * N + n) * D_IN + c]
                        : feat_free[(size_t)n * D_IN + c];
        }
        rows[r][c] = v;
    }
    __syncthreads();

    const int jj = (t & 15) * 4;          // 16 col groups
    const int r0 = (t >> 4) * 4;          // 16 row groups x 4 rows
    #pragma unroll
    for (int part = 0; part < 3; part++) {
        float acc[4][4];
        #pragma unroll
        for (int r = 0; r < 4; r++)
            #pragma unroll
            for (int u = 0; u < 4; u++) acc[r][u] = 0.f;
        #pragma unroll
        for (int c = 0; c < 32; c++) {
            float4 w = *(const float4*)&w1s[(part * 32 + c) * 64 + jj];
            #pragma unroll
            for (int r = 0; r < 4; r++) {
                float rv = rows[r0 + r][c];
                acc[r][0] += rv * w.x; acc[r][1] += rv * w.y;
                acc[r][2] += rv * w.z; acc[r][3] += rv * w.w;
            }
        }
        #pragma unroll
        for (int r = 0; r < 4; r++) {
            int q = q0 + r0 + r;
            if (q < 4 * N)
                *(float4*)(g_H + (size_t)q * 192 + part * 64 + jj) =
                    make_float4(acc[r][0], acc[r][1], acc[r][2], acc[r][3]);
        }
    }
}

// ---------------- 6: motif loss: warp per motif, loop (p, sign) ---------------
__global__ void motif_kernel(const int* __restrict__ motif,
                             const int* __restrict__ neg_uv,
                             const float* __restrict__ b1,
                             const float* __restrict__ W2,
                             const float* __restrict__ b2,
                             int N, int M) {
    __shared__ double sd[8];
    int gw = (blockIdx.x * blockDim.x + threadIdx.x) >> 5;
    int lane = threadIdx.x & 31;
    int wib = threadIdx.x >> 5;
    double local = 0.0;

    if (gw < M) {
        int m = gw;
        int u0 = motif[m], v0 = motif[M + m], w0 = motif[2 * M + m];
        int u1 = neg_uv[m], v1 = neg_uv[M + m];
        int j1 = lane + 32;
        float b1a = b1[lane], b1b = b1[j1];
        float w2a = W2[lane], w2b = W2[j1];
        float bb2 = b2[0];

        #pragma unroll
        for (int p = 0; p < 4; p++) {
            const float* base = g_H + (size_t)p * N * 192;
            #pragma unroll
            for (int s = 0; s < 2; s++) {
                int u = s ? u1 : u0;
                int v = s ? v1 : v0;
                float h0 = base[(size_t)u * 192 + lane]
                         + base[(size_t)v * 192 + 64 + lane]
                         + base[(size_t)w0 * 192 + 128 + lane] + b1a;
                float h1 = base[(size_t)u * 192 + j1]
                         + base[(size_t)v * 192 + 64 + j1]
                         + base[(size_t)w0 * 192 + 128 + j1] + b1b;
                float acc = fmaxf(h0, 0.f) * w2a + fmaxf(h1, 0.f) * w2b;
                #pragma unroll
                for (int off = 16; off; off >>= 1)
                    acc += __shfl_xor_sync(0xffffffffu, acc, off);
                if (lane == 0) {
                    float logit = acc + bb2;
                    float z = s ? -logit : logit;
                    local += (double)(fminf(z, 0.f) - log1pf(expf(-fabsf(z))));
                }
            }
        }
    }
    if (lane == 0) sd[wib] = local;
    __syncthreads();
    if (threadIdx.x == 0) {
        double sum = 0.0;
        #pragma unroll
        for (int i = 0; i < 8; i++) sum += sd[i];
        atomicAdd(&g_macc, sum);
    }
}

// ---------------- 7: contrastive-loss partial sums ----------------------------
__global__ void cl_partial_kernel(int N) {
    __shared__ double sd[256];
    int t = threadIdx.x;
    int j = blockIdx.x * 256 + t;
    double dl = 0.0;
    if (j < N) {
        float pos = g_diag[j];
        float lp = logf(pos);
        dl = (double)(2.f * lp - logf(g_colsum[j] - pos) - logf(g_rowsum[j] - pos));
    }
    sd[t] = dl;
    __syncthreads();
    #pragma unroll
    for (int s = 128; s > 0; s >>= 1) {
        if (t < s) sd[t] += sd[t + s];
        __syncthreads();
    }
    if (t == 0) atomicAdd(&g_clacc, sd[0]);
}

// ---------------- 8: combine -> scalar -----------------------------------------
__global__ void combine_kernel(float* __restrict__ out, int N, int M) {
    out[0] = (float)(-0.5 * g_clacc / (double)N - g_macc / (double)M);
}

// ---------------- launch --------------------------------------------------------
extern "C" void kernel_launch(void* const* d_in, const int* in_sizes, int n_in,
                              void* d_out, int out_size) {
    const float* x         = (const float*)d_in[0];
    const float* feats     = (const float*)d_in[1];
    const float* feat_free = (const float*)d_in[2];
    const float* ks        = (const float*)d_in[3];
    const float* Ws        = (const float*)d_in[4];
    const float* bias      = (const float*)d_in[5];
    const float* W_free    = (const float*)d_in[6];
    const float* b_free    = (const float*)d_in[7];
    const float* W1        = (const float*)d_in[8];
    const float* b1        = (const float*)d_in[9];
    const float* W2        = (const float*)d_in[10];
    const float* b2        = (const float*)d_in[11];
    const int*   motif     = (const int*)d_in[12];
    const int*   neg_uv    = (const int*)d_in[13];
    float* out = (float*)d_out;

    int N = in_sizes[0] / EMB;        // 10000
    int M = in_sizes[12] / 3;         // 50000

    cudaFuncSetAttribute(sim_hmma_kernel,
                         cudaFuncAttributeMaxDynamicSharedMemorySize, SIM_SMEM);

    // 1: normalize riemannian features
    {
        int rows = 3 * N;
        norm_feats_kernel<<<(rows * 32 + 255) / 256, 256>>>(feats, ks, N);
    }
    // 2: normalize x (warp per row; also zeros accumulators)
    norm_x_kernel<<<(N * 32 + 255) / 256, 256>>>(x, N);
    // 3: build x2
    build_x2_kernel<<<(N + X2_ROWS - 1) / X2_ROWS, 256>>>(
        feat_free, ks, Ws, bias, W_free, b_free, N);
    // 4: fused sim GEMM + reductions  (profiled slot)
    {
        dim3 grid((N + TILE - 1) / TILE, (N + TILE - 1) / TILE);
        sim_hmma_kernel<<<grid, 256, SIM_SMEM>>>(N);
    }
    // 5: H = product @ W1
    build_H_kernel<<<(4 * N + BH_ROWS - 1) / BH_ROWS, 256>>>(feat_free, W1, N);
    // 6: motif loss (warp per motif)
    motif_kernel<<<(M * 32 + 255) / 256, 256>>>(motif, neg_uv, b1, W2, b2, N, M);
    // 7: contrastive partials, 8: combine
    cl_partial_kernel<<<(N + 255) / 256, 256>>>(N);
    combine_kernel<<<1, 1>>>(out, N, M);
}